// round 2
// baseline (speedup 1.0000x reference)
#include <cuda_runtime.h>

// Problem constants
#define CB      4          // batches
#define N1C     16384      // queries per batch
#define N2C     4096       // points per batch
#define NQ      (CB*N1C)   // 65536
#define NP      (CB*N2C)   // 16384
#define COUTC   256
#define GRIDG   16
#define NCELL   (GRIDG*GRIDG*GRIDG)  // 4096

// ---------------- device scratch (static — no allocation allowed) ------------
__device__ float  g_f2pre[NP * COUTC];         // 16 MB pre-activation of branch 2
__device__ float  g_psum1[256 * COUTC];
__device__ float  g_psq1 [256 * COUTC];
__device__ float  g_psum2[64 * COUTC];
__device__ float  g_psq2 [64 * COUTC];
__device__ float  g_mean1[COUTC], g_rstd1[COUTC];
__device__ float  g_mean2[COUTC], g_rstd2[COUTC];
__device__ int    g_cnt[CB * NCELL];
__device__ int    g_cellStart[CB * (NCELL + 1)];
__device__ int    g_cellPtr[CB * NCELL];
__device__ float4 g_sortedPts[CB * N2C];       // x,y,z,|p|^2  (cell-sorted)
__device__ int    g_sortedIdx[CB * N2C];       // original row index (global)
__device__ int    g_knnIdx[NQ * 3];
__device__ float  g_knnW [NQ * 3];

// ---------------- GEMM: C = A(MxK) @ B(Kx256) + bias -----------------------
// BM=128, BN=64, BK=16, TM=8, TN=4, 256 threads
__global__ __launch_bounds__(256) void gemm_bias_kernel(
    const float* __restrict__ A, const float* __restrict__ B,
    const float* __restrict__ bias, float* __restrict__ C, int M, int K)
{
    const int N = 256;
    __shared__ float As[16][132];   // padded to reduce store bank conflicts
    __shared__ float Bs[16][64];

    int tid = threadIdx.x;
    int tx = tid & 15;          // 0..15  -> col group (x4)
    int ty = tid >> 4;          // 0..15  -> row group (x8)
    int m0 = blockIdx.y * 128;
    int n0 = blockIdx.x * 64;

    float acc[8][4];
#pragma unroll
    for (int i = 0; i < 8; i++)
#pragma unroll
        for (int j = 0; j < 4; j++) acc[i][j] = 0.f;

    int arow = tid >> 2;            // 0..63
    int acol = (tid & 3) << 2;      // 0,4,8,12
    int brow = tid >> 4;            // 0..15
    int bcol = (tid & 15) << 2;     // 0..60

    for (int k0 = 0; k0 < K; k0 += 16) {
#pragma unroll
        for (int i = 0; i < 2; i++) {
            int r = arow + (i << 6);
            float4 v = *(const float4*)(A + (size_t)(m0 + r) * K + (k0 + acol));
            As[acol + 0][r] = v.x;
            As[acol + 1][r] = v.y;
            As[acol + 2][r] = v.z;
            As[acol + 3][r] = v.w;
        }
        *(float4*)&Bs[brow][bcol] =
            *(const float4*)(B + (size_t)(k0 + brow) * N + (n0 + bcol));
        __syncthreads();

#pragma unroll
        for (int kk = 0; kk < 16; kk++) {
            float a[8], b[4];
#pragma unroll
            for (int i = 0; i < 8; i++) a[i] = As[kk][(ty << 3) + i];
#pragma unroll
            for (int j = 0; j < 4; j++) b[j] = Bs[kk][(tx << 2) + j];
#pragma unroll
            for (int i = 0; i < 8; i++)
#pragma unroll
                for (int j = 0; j < 4; j++) acc[i][j] = fmaf(a[i], b[j], acc[i][j]);
        }
        __syncthreads();
    }

    int n = n0 + (tx << 2);
    float4 bv = *(const float4*)(bias + n);
#pragma unroll
    for (int i = 0; i < 8; i++) {
        int m = m0 + (ty << 3) + i;
        float4 o;
        o.x = acc[i][0] + bv.x;
        o.y = acc[i][1] + bv.y;
        o.z = acc[i][2] + bv.z;
        o.w = acc[i][3] + bv.w;
        *(float4*)(C + (size_t)m * N + n) = o;
    }
}

// ---------------- deterministic column stats (two stage) ---------------------
__global__ __launch_bounds__(256) void colstats_partial_kernel(
    const float* __restrict__ X, float* __restrict__ ps, float* __restrict__ pq)
{
    int c = threadIdx.x, ch = blockIdx.x;
    const float* base = X + (size_t)ch * 256 * COUTC + c;
    float s = 0.f, q = 0.f;
    for (int r = 0; r < 256; r++) {
        float v = base[(size_t)r * COUTC];
        s += v;
        q = fmaf(v, v, q);
    }
    ps[ch * COUTC + c] = s;
    pq[ch * COUTC + c] = q;
}

__global__ void colstats_final_kernel(const float* __restrict__ ps,
                                      const float* __restrict__ pq,
                                      int nch, float invR,
                                      float* __restrict__ mean,
                                      float* __restrict__ rstd)
{
    int c = threadIdx.x;
    float s = 0.f, q = 0.f;
    for (int i = 0; i < nch; i++) { s += ps[i * COUTC + c]; q += pq[i * COUTC + c]; }
    float mu = s * invR;
    float var = q * invR - mu * mu;
    mean[c] = mu;
    rstd[c] = rsqrtf(var + 1e-5f);
}

// ---------------- grid build ------------------------------------------------
__device__ __forceinline__ int cell_of(float x, float y, float z, int* cx, int* cy, int* cz)
{
    int ix = min(max((int)(x * 16.f), 0), 15);
    int iy = min(max((int)(y * 16.f), 0), 15);
    int iz = min(max((int)(z * 16.f), 0), 15);
    *cx = ix; *cy = iy; *cz = iz;
    return (iz << 8) + (iy << 4) + ix;
}

__global__ void grid_zero_kernel()
{
    int i = blockIdx.x * 256 + threadIdx.x;
    if (i < CB * NCELL) g_cnt[i] = 0;
}

__global__ void grid_count_kernel(const float* __restrict__ p2)
{
    int i = blockIdx.x * 256 + threadIdx.x;
    if (i >= NP) return;
    int b = i >> 12;
    float x = p2[i * 3], y = p2[i * 3 + 1], z = p2[i * 3 + 2];
    int cx, cy, cz;
    int cell = cell_of(x, y, z, &cx, &cy, &cz);
    atomicAdd(&g_cnt[b * NCELL + cell], 1);
}

__global__ __launch_bounds__(1024) void grid_scan_kernel()
{
    __shared__ int ts[1024];
    int b = blockIdx.x, t = threadIdx.x;
    int v0 = g_cnt[b * NCELL + t * 4 + 0];
    int v1 = g_cnt[b * NCELL + t * 4 + 1];
    int v2 = g_cnt[b * NCELL + t * 4 + 2];
    int v3 = g_cnt[b * NCELL + t * 4 + 3];
    int loc = v0 + v1 + v2 + v3;
    ts[t] = loc;
    __syncthreads();
    for (int off = 1; off < 1024; off <<= 1) {
        int add = (t >= off) ? ts[t - off] : 0;
        __syncthreads();
        ts[t] += add;
        __syncthreads();
    }
    int excl = ts[t] - loc;
    int base = b * (NCELL + 1);
    int p = excl;
    g_cellStart[base + t * 4 + 0] = p; g_cellPtr[b * NCELL + t * 4 + 0] = p; p += v0;
    g_cellStart[base + t * 4 + 1] = p; g_cellPtr[b * NCELL + t * 4 + 1] = p; p += v1;
    g_cellStart[base + t * 4 + 2] = p; g_cellPtr[b * NCELL + t * 4 + 2] = p; p += v2;
    g_cellStart[base + t * 4 + 3] = p; g_cellPtr[b * NCELL + t * 4 + 3] = p; p += v3;
    if (t == 1023) g_cellStart[base + NCELL] = ts[1023];
}

__global__ void grid_scatter_kernel(const float* __restrict__ p2)
{
    int i = blockIdx.x * 256 + threadIdx.x;
    if (i >= NP) return;
    int b = i >> 12;
    float x = p2[i * 3], y = p2[i * 3 + 1], z = p2[i * 3 + 2];
    // |p|^2 with the reference's rounding: fl(fl(x*x)+fl(y*y))+fl(z*z)
    float pp = __fadd_rn(__fadd_rn(__fmul_rn(x, x), __fmul_rn(y, y)), __fmul_rn(z, z));
    int cx, cy, cz;
    int cell = cell_of(x, y, z, &cx, &cy, &cz);
    int pos = atomicAdd(&g_cellPtr[b * NCELL + cell], 1);
    g_sortedPts[b * N2C + pos] = make_float4(x, y, z, pp);
    g_sortedIdx[b * N2C + pos] = i;   // original global row
}

// Make within-cell order deterministic (ascending original index).
__global__ void grid_sortfix_kernel()
{
    int t = blockIdx.x * 256 + threadIdx.x;
    if (t >= CB * NCELL) return;
    int b = t >> 12, cell = t & 4095;
    int s = g_cellStart[b * (NCELL + 1) + cell];
    int e = g_cellStart[b * (NCELL + 1) + cell + 1];
    int base = b * N2C;
    for (int a = s + 1; a < e; a++) {
        int ia = g_sortedIdx[base + a];
        float4 pa = g_sortedPts[base + a];
        int k = a - 1;
        while (k >= s && g_sortedIdx[base + k] > ia) {
            g_sortedIdx[base + k + 1] = g_sortedIdx[base + k];
            g_sortedPts[base + k + 1] = g_sortedPts[base + k];
            k--;
        }
        g_sortedIdx[base + k + 1] = ia;
        g_sortedPts[base + k + 1] = pa;
    }
}

// ---------------- KNN (K=3) via grid ring expansion --------------------------
// Exactly emulates the reference rounding:
//   qq = fl(fl(x^2)+fl(y^2))+fl(z^2)        (same for pp)
//   dot = fma(q2,p2, fma(q1,p1, fl(q0*p0)))  (cublas k-ascending fma chain)
//   d2  = fl(fl(qq+pp) - fl(2*dot))
// Ties broken by lower original index (top_k semantics).
__global__ __launch_bounds__(256) void knn_kernel(const float* __restrict__ p1)
{
    extern __shared__ unsigned char smraw[];
    float4* sp = (float4*)smraw;                                  // 4096 float4
    int* cs  = (int*)(smraw + N2C * sizeof(float4));              // 4097 ints
    int* sid = (int*)(smraw + N2C * sizeof(float4) + (NCELL + 16) * sizeof(int)); // 4096 ints

    int batch = blockIdx.x >> 6;
    for (int i = threadIdx.x; i < N2C; i += 256) {
        sp[i]  = g_sortedPts[batch * N2C + i];
        sid[i] = g_sortedIdx[batch * N2C + i];
    }
    for (int i = threadIdx.x; i < NCELL + 1; i += 256)
        cs[i] = g_cellStart[batch * (NCELL + 1) + i];
    __syncthreads();

    int qrow = batch * N1C + ((blockIdx.x & 63) << 8) + threadIdx.x;
    float qx = p1[qrow * 3 + 0];
    float qy = p1[qrow * 3 + 1];
    float qz = p1[qrow * 3 + 2];
    float qq = __fadd_rn(__fadd_rn(__fmul_rn(qx, qx), __fmul_rn(qy, qy)), __fmul_rn(qz, qz));

    int cx, cy, cz;
    (void)cell_of(qx, qy, qz, &cx, &cy, &cz);

    float b0 = 3.4e38f, b1 = 3.4e38f, b2 = 3.4e38f;
    int i0 = 0x7fffffff, i1 = 0x7fffffff, i2 = 0x7fffffff;

    auto proc = [&](int s, int e) {
        for (int j = s; j < e; j++) {
            float4 p = sp[j];
            int oi = sid[j];
            float dot = fmaf(qz, p.z, fmaf(qy, p.y, __fmul_rn(qx, p.x)));
            float d2 = __fsub_rn(__fadd_rn(qq, p.w), __fmul_rn(2.0f, dot));
            bool lt2 = (d2 < b2) || (d2 == b2 && oi < i2);
            if (lt2) {
                bool lt1 = (d2 < b1) || (d2 == b1 && oi < i1);
                if (lt1) {
                    b2 = b1; i2 = i1;
                    bool lt0 = (d2 < b0) || (d2 == b0 && oi < i0);
                    if (lt0) { b1 = b0; i1 = i0; b0 = d2; i0 = oi; }
                    else     { b1 = d2; i1 = oi; }
                } else { b2 = d2; i2 = oi; }
            }
        }
    };

    const float h = 0.0625f;
    int rmax = max(max(cx, 15 - cx), max(max(cy, 15 - cy), max(cz, 15 - cz)));
    for (int r = 0; r <= rmax; r++) {
        if (r > 0) {
            float bnd = (float)(r - 1) * h;   // all unvisited points are >= bnd away
            if (b2 <= bnd * bnd - 1e-6f) break;   // slack for fp32 rounding of d2
        }
        int zlo = max(cz - r, 0), zhi = min(cz + r, 15);
        for (int z = zlo; z <= zhi; z++) {
            bool ze = (z == cz - r) || (z == cz + r);
            int ylo = max(cy - r, 0), yhi = min(cy + r, 15);
            for (int y = ylo; y <= yhi; y++) {
                bool ye = (y == cy - r) || (y == cy + r);
                int rb = (z << 8) + (y << 4);
                if (ze || ye) {
                    int xlo = max(cx - r, 0), xhi = min(cx + r, 15);
                    proc(cs[rb + xlo], cs[rb + xhi + 1]);   // contiguous x-span
                } else {
                    if (cx - r >= 0) proc(cs[rb + cx - r], cs[rb + cx - r + 1]);
                    if (cx + r <= 15) proc(cs[rb + cx + r], cs[rb + cx + r + 1]);
                }
            }
        }
    }

    // Reference weight math with exact fp32 rounding:
    // dist = max(d2, 0); r = 1/(dist + 1e-8); w = r / ((r0+r1)+r2)
    float d0 = fmaxf(b0, 0.f), d1 = fmaxf(b1, 0.f), d2c = fmaxf(b2, 0.f);
    float r0 = __fdiv_rn(1.0f, __fadd_rn(d0, 1e-8f));
    float r1 = __fdiv_rn(1.0f, __fadd_rn(d1, 1e-8f));
    float r2 = __fdiv_rn(1.0f, __fadd_rn(d2c, 1e-8f));
    float sum = __fadd_rn(__fadd_rn(r0, r1), r2);

    g_knnIdx[qrow * 3 + 0] = i0;
    g_knnIdx[qrow * 3 + 1] = i1;
    g_knnIdx[qrow * 3 + 2] = i2;
    g_knnW[qrow * 3 + 0] = __fdiv_rn(r0, sum);
    g_knnW[qrow * 3 + 1] = __fdiv_rn(r1, sum);
    g_knnW[qrow * 3 + 2] = __fdiv_rn(r2, sum);
}

// ---------------- final: BN+relu both branches, gather, weighted add ---------
__global__ __launch_bounds__(256) void final_kernel(
    float* io,
    const float* __restrict__ ga1, const float* __restrict__ be1,
    const float* __restrict__ ga2, const float* __restrict__ be2)
{
    int row = blockIdx.x, c = threadIdx.x;
    __shared__ int si[3];
    __shared__ float sw[3];
    if (c < 3) { si[c] = g_knnIdx[row * 3 + c]; sw[c] = g_knnW[row * 3 + c]; }
    __syncthreads();

    float x = io[(size_t)row * COUTC + c];
    float v1 = fmaxf(ga1[c] * (x - g_mean1[c]) * g_rstd1[c] + be1[c], 0.f);

    float acc = 0.f;
#pragma unroll
    for (int k = 0; k < 3; k++) {
        float y = g_f2pre[(size_t)si[k] * COUTC + c];
        float v = fmaxf(ga2[c] * (y - g_mean2[c]) * g_rstd2[c] + be2[c], 0.f);
        acc = fmaf(sw[k], v, acc);
    }
    io[(size_t)row * COUTC + c] = v1 + acc;
}

// ---------------- launch ----------------------------------------------------
extern "C" void kernel_launch(void* const* d_in, const int* in_sizes, int n_in,
                              void* d_out, int out_size)
{
    const float* p1  = (const float*)d_in[0];
    const float* f1  = (const float*)d_in[1];
    const float* p2  = (const float*)d_in[2];
    const float* f2  = (const float*)d_in[3];
    const float* W1  = (const float*)d_in[4];
    const float* b1  = (const float*)d_in[5];
    const float* ga1 = (const float*)d_in[6];
    const float* be1 = (const float*)d_in[7];
    const float* W2  = (const float*)d_in[8];
    const float* b2  = (const float*)d_in[9];
    const float* ga2 = (const float*)d_in[10];
    const float* be2 = (const float*)d_in[11];
    float* out = (float*)d_out;

    float *f2pre, *ps1, *pq1, *ps2, *pq2, *mean1, *rstd1, *mean2, *rstd2;
    cudaGetSymbolAddress((void**)&f2pre, g_f2pre);
    cudaGetSymbolAddress((void**)&ps1, g_psum1);
    cudaGetSymbolAddress((void**)&pq1, g_psq1);
    cudaGetSymbolAddress((void**)&ps2, g_psum2);
    cudaGetSymbolAddress((void**)&pq2, g_psq2);
    cudaGetSymbolAddress((void**)&mean1, g_mean1);
    cudaGetSymbolAddress((void**)&rstd1, g_rstd1);
    cudaGetSymbolAddress((void**)&mean2, g_mean2);
    cudaGetSymbolAddress((void**)&rstd2, g_rstd2);

    // Branch GEMMs
    gemm_bias_kernel<<<dim3(4, 512), 256>>>(f1, W1, b1, out, NQ, 256);
    gemm_bias_kernel<<<dim3(4, 128), 256>>>(f2, W2, b2, f2pre, NP, 512);

    // BN stats (deterministic)
    colstats_partial_kernel<<<256, 256>>>(out, ps1, pq1);
    colstats_partial_kernel<<<64, 256>>>(f2pre, ps2, pq2);
    colstats_final_kernel<<<1, 256>>>(ps1, pq1, 256, 1.f / (float)NQ, mean1, rstd1);
    colstats_final_kernel<<<1, 256>>>(ps2, pq2, 64, 1.f / (float)NP, mean2, rstd2);

    // Spatial grid
    grid_zero_kernel<<<64, 256>>>();
    grid_count_kernel<<<64, 256>>>(p2);
    grid_scan_kernel<<<4, 1024>>>();
    grid_scatter_kernel<<<64, 256>>>(p2);
    grid_sortfix_kernel<<<64, 256>>>();

    // KNN  (smem: points 64KB + cellStart 16KB + ids 16KB)
    size_t sm = N2C * sizeof(float4) + (NCELL + 16) * sizeof(int) + N2C * sizeof(int);
    cudaFuncSetAttribute(knn_kernel, cudaFuncAttributeMaxDynamicSharedMemorySize, (int)sm);
    knn_kernel<<<256, 256, sm>>>(p1);

    // Fused epilogue
    final_kernel<<<NQ, 256>>>(out, ga1, be1, ga2, be2);
}

// round 4
// speedup vs baseline: 1.4376x; 1.4376x over previous
#include <cuda_runtime.h>
#include <cuda_bf16.h>
#include <cstdint>

// Problem constants
#define CB      4          // batches
#define N1C     16384      // queries per batch
#define N2C     4096       // points per batch
#define NQ      (CB*N1C)   // 65536
#define NP      (CB*N2C)   // 16384
#define COUTC   256
#define GRIDG   16
#define NCELL   (GRIDG*GRIDG*GRIDG)  // 4096

__device__ __forceinline__ uint32_t smem_to_u32(const void* smem_ptr) {
    uint32_t addr;
    asm("{ .reg .u64 tmp; cvta.to.shared.u64 tmp, %1; cvt.u32.u64 %0, tmp; }"
        : "=r"(addr) : "l"(smem_ptr));
    return addr;
}
__device__ __forceinline__ void ldm_x4(uint32_t* r, uint32_t addr) {
    asm volatile("ldmatrix.sync.aligned.m8n8.x4.shared.b16 {%0,%1,%2,%3}, [%4];"
        : "=r"(r[0]), "=r"(r[1]), "=r"(r[2]), "=r"(r[3]) : "r"(addr));
}
__device__ __forceinline__ void ldm_x2(uint32_t* r, uint32_t addr) {
    asm volatile("ldmatrix.sync.aligned.m8n8.x2.shared.b16 {%0,%1}, [%2];"
        : "=r"(r[0]), "=r"(r[1]) : "r"(addr));
}
__device__ __forceinline__ void mma_bf16(float* c, const uint32_t* a, const uint32_t* b) {
    asm volatile("mma.sync.aligned.m16n8k16.row.col.f32.bf16.bf16.f32 "
        "{%0,%1,%2,%3}, {%4,%5,%6,%7}, {%8,%9}, {%0,%1,%2,%3};"
        : "+f"(c[0]), "+f"(c[1]), "+f"(c[2]), "+f"(c[3])
        : "r"(a[0]), "r"(a[1]), "r"(a[2]), "r"(a[3]), "r"(b[0]), "r"(b[1]));
}

// ---------------- device scratch (static — no allocation allowed) ------------
__device__ float  g_f2pre[NP * COUTC];         // 16 MB pre-activation of branch 2
__device__ __nv_bfloat16 g_A1h[NQ * 256];
__device__ __nv_bfloat16 g_A1l[NQ * 256];
__device__ __nv_bfloat16 g_A2h[NP * 512];
__device__ __nv_bfloat16 g_A2l[NP * 512];
__device__ __nv_bfloat16 g_W1h[256 * 256];     // transposed [N][K]
__device__ __nv_bfloat16 g_W1l[256 * 256];
__device__ __nv_bfloat16 g_W2h[256 * 512];
__device__ __nv_bfloat16 g_W2l[256 * 512];
__device__ float  g_psum1[1024 * COUTC];
__device__ float  g_psq1 [1024 * COUTC];
__device__ float  g_psum2[256 * COUTC];
__device__ float  g_psq2 [256 * COUTC];
__device__ float  g_mean1[COUTC], g_rstd1[COUTC];
__device__ float  g_mean2[COUTC], g_rstd2[COUTC];
__device__ int    g_cnt[CB * NCELL];
__device__ int    g_cellStart[CB * (NCELL + 1)];
__device__ int    g_cellPtr[CB * NCELL];
__device__ float4 g_sortedPts[CB * N2C];       // x,y,z,|p|^2  (cell-sorted)
__device__ int    g_sortedIdx[CB * N2C];       // original row index (global)
__device__ int    g_knnIdx[NQ * 3];
__device__ float  g_knnW [NQ * 3];

// ---------------- fp32 -> bf16 hi/lo split -----------------------------------
__global__ __launch_bounds__(256) void split_kernel(
    const float* __restrict__ x, __nv_bfloat16* __restrict__ hi,
    __nv_bfloat16* __restrict__ lo, int n4)
{
    int i = blockIdx.x * 256 + threadIdx.x;
    if (i >= n4) return;
    float4 v = ((const float4*)x)[i];
    __nv_bfloat16 h0 = __float2bfloat16_rn(v.x);
    __nv_bfloat16 h1 = __float2bfloat16_rn(v.y);
    __nv_bfloat16 h2 = __float2bfloat16_rn(v.z);
    __nv_bfloat16 h3 = __float2bfloat16_rn(v.w);
    __nv_bfloat16 l0 = __float2bfloat16_rn(v.x - __bfloat162float(h0));
    __nv_bfloat16 l1 = __float2bfloat16_rn(v.y - __bfloat162float(h1));
    __nv_bfloat16 l2 = __float2bfloat16_rn(v.z - __bfloat162float(h2));
    __nv_bfloat16 l3 = __float2bfloat16_rn(v.w - __bfloat162float(h3));
    __nv_bfloat162* H = (__nv_bfloat162*)hi;
    __nv_bfloat162* L = (__nv_bfloat162*)lo;
    H[2*i]   = __nv_bfloat162(h0, h1);
    H[2*i+1] = __nv_bfloat162(h2, h3);
    L[2*i]   = __nv_bfloat162(l0, l1);
    L[2*i+1] = __nv_bfloat162(l2, l3);
}

// transpose W[K][N] -> WT[N][K], with hi/lo split (small matrices)
__global__ __launch_bounds__(256) void wt_split_kernel(
    const float* __restrict__ W, __nv_bfloat16* __restrict__ th,
    __nv_bfloat16* __restrict__ tl, int K, int N)
{
    int i = blockIdx.x * 256 + threadIdx.x;
    if (i >= K * N) return;
    int k = i / N, n = i % N;
    float x = W[i];
    __nv_bfloat16 h = __float2bfloat16_rn(x);
    th[n * K + k] = h;
    tl[n * K + k] = __float2bfloat16_rn(x - __bfloat162float(h));
}

// ---------------- mma.sync bf16x3 GEMM --------------------------------------
// C[M,256] = A[M,K] @ WT[256,K]^T + bias.   D += Ah*Bh + Ah*Bl + Al*Bh.
// Block 128x128, BK=32, 8 warps (2m x 4n), warp tile 64x32 (4x4 m16n8k16).
#define PITCH 40   // bf16 elements per smem row (80B — conflict-free ldmatrix)

template<int K>
__global__ __launch_bounds__(256) void gemm_mma_kernel(
    const __nv_bfloat16* __restrict__ Ah, const __nv_bfloat16* __restrict__ Al,
    const __nv_bfloat16* __restrict__ Bh, const __nv_bfloat16* __restrict__ Bl,
    const float* __restrict__ bias, float* __restrict__ C)
{
    __shared__ __nv_bfloat16 sAh[128 * PITCH], sAl[128 * PITCH];
    __shared__ __nv_bfloat16 sBh[128 * PITCH], sBl[128 * PITCH];

    const int tid = threadIdx.x, lane = tid & 31, wid = tid >> 5;
    const int wm = wid & 1, wn = wid >> 1;      // warp grid: 2 (m) x 4 (n)
    const int m0 = blockIdx.y * 128, n0 = blockIdx.x * 128;

    const uint32_t uAh = smem_to_u32(sAh), uAl = smem_to_u32(sAl);
    const uint32_t uBh = smem_to_u32(sBh), uBl = smem_to_u32(sBl);

    float acc[4][4][4];
#pragma unroll
    for (int i = 0; i < 4; i++)
#pragma unroll
        for (int j = 0; j < 4; j++)
#pragma unroll
            for (int k = 0; k < 4; k++) acc[i][j][k] = 0.f;

    const int lrow = tid >> 2, lq = tid & 3;    // gmem->smem: row 0..63, quad 0..3

    // ldmatrix per-lane byte offsets (within a tile array)
    const uint32_t aoff = ((uint32_t)((wm * 64 + (lane & 15)) * PITCH + (lane >> 4) * 8)) * 2;
    const uint32_t boff = ((uint32_t)((wn * 32 + (lane & 7)) * PITCH + ((lane >> 3) & 1) * 8)) * 2;

    for (int k0 = 0; k0 < K; k0 += 32) {
#pragma unroll
        for (int rep = 0; rep < 2; rep++) {
            int row = lrow + rep * 64;
            size_t ga = (size_t)(m0 + row) * K + k0 + lq * 8;
            size_t gb = (size_t)(n0 + row) * K + k0 + lq * 8;
            int so = row * PITCH + lq * 8;
            *(uint4*)(sAh + so) = *(const uint4*)(Ah + ga);
            *(uint4*)(sAl + so) = *(const uint4*)(Al + ga);
            *(uint4*)(sBh + so) = *(const uint4*)(Bh + gb);
            *(uint4*)(sBl + so) = *(const uint4*)(Bl + gb);
        }
        __syncthreads();

#pragma unroll
        for (int ks = 0; ks < 2; ks++) {
            uint32_t afh[4][4], afl[4][4], bfh[4][2], bfl[4][2];
#pragma unroll
            for (int mt = 0; mt < 4; mt++) {
                uint32_t o = aoff + (uint32_t)(mt * 16 * PITCH + ks * 16) * 2;
                ldm_x4(afh[mt], uAh + o);
                ldm_x4(afl[mt], uAl + o);
            }
#pragma unroll
            for (int nt = 0; nt < 4; nt++) {
                uint32_t o = boff + (uint32_t)(nt * 8 * PITCH + ks * 16) * 2;
                ldm_x2(bfh[nt], uBh + o);
                ldm_x2(bfl[nt], uBl + o);
            }
#pragma unroll
            for (int mt = 0; mt < 4; mt++)
#pragma unroll
                for (int nt = 0; nt < 4; nt++) {
                    mma_bf16(acc[mt][nt], afh[mt], bfh[nt]);
                    mma_bf16(acc[mt][nt], afh[mt], bfl[nt]);
                    mma_bf16(acc[mt][nt], afl[mt], bfh[nt]);
                }
        }
        __syncthreads();
    }

    // epilogue: registers -> gmem with bias
    const int tr = lane >> 2, tc = (lane & 3) * 2;
    const int rbase = m0 + wm * 64, cbase = n0 + wn * 32;
#pragma unroll
    for (int nt = 0; nt < 4; nt++) {
        int col = cbase + nt * 8 + tc;
        float bx = bias[col], by = bias[col + 1];
#pragma unroll
        for (int mt = 0; mt < 4; mt++) {
            int row = rbase + mt * 16 + tr;
            float2 v0 = make_float2(acc[mt][nt][0] + bx, acc[mt][nt][1] + by);
            float2 v1 = make_float2(acc[mt][nt][2] + bx, acc[mt][nt][3] + by);
            *(float2*)(C + (size_t)row * 256 + col) = v0;
            *(float2*)(C + (size_t)(row + 8) * 256 + col) = v1;
        }
    }
}

// ---------------- deterministic column stats (two stage) ---------------------
__global__ __launch_bounds__(256) void colstats_partial_kernel(
    const float* __restrict__ X, float* __restrict__ ps, float* __restrict__ pq)
{
    int c = threadIdx.x, ch = blockIdx.x;
    const float* base = X + (size_t)ch * 64 * COUTC + c;
    float s = 0.f, q = 0.f;
#pragma unroll 8
    for (int r = 0; r < 64; r++) {
        float v = base[(size_t)r * COUTC];
        s += v;
        q = fmaf(v, v, q);
    }
    ps[ch * COUTC + c] = s;
    pq[ch * COUTC + c] = q;
}

__global__ __launch_bounds__(128) void colstats_final_kernel(
    const float* __restrict__ ps, const float* __restrict__ pq,
    int nch, float invR, float* __restrict__ mean, float* __restrict__ rstd)
{
    int c = blockIdx.x, t = threadIdx.x;
    float s = 0.f, q = 0.f;
    for (int i = t; i < nch; i += 128) { s += ps[i * COUTC + c]; q += pq[i * COUTC + c]; }
    __shared__ float ss[128], sq[128];
    ss[t] = s; sq[t] = q;
    __syncthreads();
    for (int o = 64; o > 0; o >>= 1) {
        if (t < o) { ss[t] += ss[t + o]; sq[t] += sq[t + o]; }
        __syncthreads();
    }
    if (t == 0) {
        float mu = ss[0] * invR;
        float var = sq[0] * invR - mu * mu;
        mean[c] = mu;
        rstd[c] = rsqrtf(var + 1e-5f);
    }
}

// ---------------- grid build ------------------------------------------------
__device__ __forceinline__ int cell_of(float x, float y, float z, int* cx, int* cy, int* cz)
{
    int ix = min(max((int)(x * 16.f), 0), 15);
    int iy = min(max((int)(y * 16.f), 0), 15);
    int iz = min(max((int)(z * 16.f), 0), 15);
    *cx = ix; *cy = iy; *cz = iz;
    return (iz << 8) + (iy << 4) + ix;
}

__global__ void grid_zero_kernel()
{
    int i = blockIdx.x * 256 + threadIdx.x;
    if (i < CB * NCELL) g_cnt[i] = 0;
}

__global__ void grid_count_kernel(const float* __restrict__ p2)
{
    int i = blockIdx.x * 256 + threadIdx.x;
    if (i >= NP) return;
    int b = i >> 12;
    float x = p2[i * 3], y = p2[i * 3 + 1], z = p2[i * 3 + 2];
    int cx, cy, cz;
    int cell = cell_of(x, y, z, &cx, &cy, &cz);
    atomicAdd(&g_cnt[b * NCELL + cell], 1);
}

__global__ __launch_bounds__(1024) void grid_scan_kernel()
{
    __shared__ int ts[1024];
    int b = blockIdx.x, t = threadIdx.x;
    int v0 = g_cnt[b * NCELL + t * 4 + 0];
    int v1 = g_cnt[b * NCELL + t * 4 + 1];
    int v2 = g_cnt[b * NCELL + t * 4 + 2];
    int v3 = g_cnt[b * NCELL + t * 4 + 3];
    int loc = v0 + v1 + v2 + v3;
    ts[t] = loc;
    __syncthreads();
    for (int off = 1; off < 1024; off <<= 1) {
        int add = (t >= off) ? ts[t - off] : 0;
        __syncthreads();
        ts[t] += add;
        __syncthreads();
    }
    int excl = ts[t] - loc;
    int base = b * (NCELL + 1);
    int p = excl;
    g_cellStart[base + t * 4 + 0] = p; g_cellPtr[b * NCELL + t * 4 + 0] = p; p += v0;
    g_cellStart[base + t * 4 + 1] = p; g_cellPtr[b * NCELL + t * 4 + 1] = p; p += v1;
    g_cellStart[base + t * 4 + 2] = p; g_cellPtr[b * NCELL + t * 4 + 2] = p; p += v2;
    g_cellStart[base + t * 4 + 3] = p; g_cellPtr[b * NCELL + t * 4 + 3] = p; p += v3;
    if (t == 1023) g_cellStart[base + NCELL] = ts[1023];
}

__global__ void grid_scatter_kernel(const float* __restrict__ p2)
{
    int i = blockIdx.x * 256 + threadIdx.x;
    if (i >= NP) return;
    int b = i >> 12;
    float x = p2[i * 3], y = p2[i * 3 + 1], z = p2[i * 3 + 2];
    // |p|^2 with the reference's rounding: fl(fl(x*x)+fl(y*y))+fl(z*z)
    float pp = __fadd_rn(__fadd_rn(__fmul_rn(x, x), __fmul_rn(y, y)), __fmul_rn(z, z));
    int cx, cy, cz;
    int cell = cell_of(x, y, z, &cx, &cy, &cz);
    int pos = atomicAdd(&g_cellPtr[b * NCELL + cell], 1);
    g_sortedPts[b * N2C + pos] = make_float4(x, y, z, pp);
    g_sortedIdx[b * N2C + pos] = i;   // original global row
}

// Make within-cell order deterministic (ascending original index).
__global__ void grid_sortfix_kernel()
{
    int t = blockIdx.x * 256 + threadIdx.x;
    if (t >= CB * NCELL) return;
    int b = t >> 12, cell = t & 4095;
    int s = g_cellStart[b * (NCELL + 1) + cell];
    int e = g_cellStart[b * (NCELL + 1) + cell + 1];
    int base = b * N2C;
    for (int a = s + 1; a < e; a++) {
        int ia = g_sortedIdx[base + a];
        float4 pa = g_sortedPts[base + a];
        int k = a - 1;
        while (k >= s && g_sortedIdx[base + k] > ia) {
            g_sortedIdx[base + k + 1] = g_sortedIdx[base + k];
            g_sortedPts[base + k + 1] = g_sortedPts[base + k];
            k--;
        }
        g_sortedIdx[base + k + 1] = ia;
        g_sortedPts[base + k + 1] = pa;
    }
}

// ---------------- KNN (K=3) via grid ring expansion --------------------------
// Exactly emulates reference rounding (rn intrinsics, contraction-proof).
__global__ __launch_bounds__(256) void knn_kernel(const float* __restrict__ p1)
{
    extern __shared__ unsigned char smraw[];
    float4* sp = (float4*)smraw;                                  // 4096 float4
    int* cs  = (int*)(smraw + N2C * sizeof(float4));              // 4097 ints
    int* sid = (int*)(smraw + N2C * sizeof(float4) + (NCELL + 16) * sizeof(int)); // 4096 ints

    int batch = blockIdx.x >> 6;
    for (int i = threadIdx.x; i < N2C; i += 256) {
        sp[i]  = g_sortedPts[batch * N2C + i];
        sid[i] = g_sortedIdx[batch * N2C + i];
    }
    for (int i = threadIdx.x; i < NCELL + 1; i += 256)
        cs[i] = g_cellStart[batch * (NCELL + 1) + i];
    __syncthreads();

    int qrow = batch * N1C + ((blockIdx.x & 63) << 8) + threadIdx.x;
    float qx = p1[qrow * 3 + 0];
    float qy = p1[qrow * 3 + 1];
    float qz = p1[qrow * 3 + 2];
    float qq = __fadd_rn(__fadd_rn(__fmul_rn(qx, qx), __fmul_rn(qy, qy)), __fmul_rn(qz, qz));

    int cx, cy, cz;
    (void)cell_of(qx, qy, qz, &cx, &cy, &cz);

    float b0 = 3.4e38f, b1 = 3.4e38f, b2 = 3.4e38f;
    int i0 = 0x7fffffff, i1 = 0x7fffffff, i2 = 0x7fffffff;

    auto proc = [&](int s, int e) {
        for (int j = s; j < e; j++) {
            float4 p = sp[j];
            int oi = sid[j];
            float dot = fmaf(qz, p.z, fmaf(qy, p.y, __fmul_rn(qx, p.x)));
            float d2 = __fsub_rn(__fadd_rn(qq, p.w), __fmul_rn(2.0f, dot));
            bool lt2 = (d2 < b2) || (d2 == b2 && oi < i2);
            if (lt2) {
                bool lt1 = (d2 < b1) || (d2 == b1 && oi < i1);
                if (lt1) {
                    b2 = b1; i2 = i1;
                    bool lt0 = (d2 < b0) || (d2 == b0 && oi < i0);
                    if (lt0) { b1 = b0; i1 = i0; b0 = d2; i0 = oi; }
                    else     { b1 = d2; i1 = oi; }
                } else { b2 = d2; i2 = oi; }
            }
        }
    };

    const float h = 0.0625f;
    int rmax = max(max(cx, 15 - cx), max(max(cy, 15 - cy), max(cz, 15 - cz)));
    for (int r = 0; r <= rmax; r++) {
        if (r > 0) {
            float bnd = (float)(r - 1) * h;   // all unvisited points are >= bnd away
            if (b2 <= bnd * bnd - 1e-6f) break;   // slack for fp32 rounding of d2
        }
        int zlo = max(cz - r, 0), zhi = min(cz + r, 15);
        for (int z = zlo; z <= zhi; z++) {
            bool ze = (z == cz - r) || (z == cz + r);
            int ylo = max(cy - r, 0), yhi = min(cy + r, 15);
            for (int y = ylo; y <= yhi; y++) {
                bool ye = (y == cy - r) || (y == cy + r);
                int rb = (z << 8) + (y << 4);
                if (ze || ye) {
                    int xlo = max(cx - r, 0), xhi = min(cx + r, 15);
                    proc(cs[rb + xlo], cs[rb + xhi + 1]);   // contiguous x-span
                } else {
                    if (cx - r >= 0) proc(cs[rb + cx - r], cs[rb + cx - r + 1]);
                    if (cx + r <= 15) proc(cs[rb + cx + r], cs[rb + cx + r + 1]);
                }
            }
        }
    }

    float d0 = fmaxf(b0, 0.f), d1 = fmaxf(b1, 0.f), d2c = fmaxf(b2, 0.f);
    float r0 = __fdiv_rn(1.0f, __fadd_rn(d0, 1e-8f));
    float r1 = __fdiv_rn(1.0f, __fadd_rn(d1, 1e-8f));
    float r2 = __fdiv_rn(1.0f, __fadd_rn(d2c, 1e-8f));
    float sum = __fadd_rn(__fadd_rn(r0, r1), r2);

    g_knnIdx[qrow * 3 + 0] = i0;
    g_knnIdx[qrow * 3 + 1] = i1;
    g_knnIdx[qrow * 3 + 2] = i2;
    g_knnW[qrow * 3 + 0] = __fdiv_rn(r0, sum);
    g_knnW[qrow * 3 + 1] = __fdiv_rn(r1, sum);
    g_knnW[qrow * 3 + 2] = __fdiv_rn(r2, sum);
}

// ---------------- final: BN+relu both branches, gather, weighted add ---------
__global__ __launch_bounds__(256) void final_kernel(
    float* io,
    const float* __restrict__ ga1, const float* __restrict__ be1,
    const float* __restrict__ ga2, const float* __restrict__ be2)
{
    int row = blockIdx.x, c = threadIdx.x;
    __shared__ int si[3];
    __shared__ float sw[3];
    if (c < 3) { si[c] = g_knnIdx[row * 3 + c]; sw[c] = g_knnW[row * 3 + c]; }
    __syncthreads();

    float x = io[(size_t)row * COUTC + c];
    float v1 = fmaxf(ga1[c] * (x - g_mean1[c]) * g_rstd1[c] + be1[c], 0.f);

    float acc = 0.f;
#pragma unroll
    for (int k = 0; k < 3; k++) {
        float y = g_f2pre[(size_t)si[k] * COUTC + c];
        float v = fmaxf(ga2[c] * (y - g_mean2[c]) * g_rstd2[c] + be2[c], 0.f);
        acc = fmaf(sw[k], v, acc);
    }
    io[(size_t)row * COUTC + c] = v1 + acc;
}

// ---------------- launch ----------------------------------------------------
extern "C" void kernel_launch(void* const* d_in, const int* in_sizes, int n_in,
                              void* d_out, int out_size)
{
    const float* p1  = (const float*)d_in[0];
    const float* f1  = (const float*)d_in[1];
    const float* p2  = (const float*)d_in[2];
    const float* f2  = (const float*)d_in[3];
    const float* W1  = (const float*)d_in[4];
    const float* b1  = (const float*)d_in[5];
    const float* ga1 = (const float*)d_in[6];
    const float* be1 = (const float*)d_in[7];
    const float* W2  = (const float*)d_in[8];
    const float* b2  = (const float*)d_in[9];
    const float* ga2 = (const float*)d_in[10];
    const float* be2 = (const float*)d_in[11];
    float* out = (float*)d_out;

    float *f2pre, *ps1, *pq1, *ps2, *pq2, *mean1, *rstd1, *mean2, *rstd2;
    __nv_bfloat16 *a1h, *a1l, *a2h, *a2l, *w1h, *w1l, *w2h, *w2l;
    cudaGetSymbolAddress((void**)&f2pre, g_f2pre);
    cudaGetSymbolAddress((void**)&ps1, g_psum1);
    cudaGetSymbolAddress((void**)&pq1, g_psq1);
    cudaGetSymbolAddress((void**)&ps2, g_psum2);
    cudaGetSymbolAddress((void**)&pq2, g_psq2);
    cudaGetSymbolAddress((void**)&mean1, g_mean1);
    cudaGetSymbolAddress((void**)&rstd1, g_rstd1);
    cudaGetSymbolAddress((void**)&mean2, g_mean2);
    cudaGetSymbolAddress((void**)&rstd2, g_rstd2);
    cudaGetSymbolAddress((void**)&a1h, g_A1h);
    cudaGetSymbolAddress((void**)&a1l, g_A1l);
    cudaGetSymbolAddress((void**)&a2h, g_A2h);
    cudaGetSymbolAddress((void**)&a2l, g_A2l);
    cudaGetSymbolAddress((void**)&w1h, g_W1h);
    cudaGetSymbolAddress((void**)&w1l, g_W1l);
    cudaGetSymbolAddress((void**)&w2h, g_W2h);
    cudaGetSymbolAddress((void**)&w2l, g_W2l);

    // bf16 hi/lo splits
    split_kernel<<<(NQ * 256 / 4 + 255) / 256, 256>>>(f1, a1h, a1l, NQ * 256 / 4);
    split_kernel<<<(NP * 512 / 4 + 255) / 256, 256>>>(f2, a2h, a2l, NP * 512 / 4);
    wt_split_kernel<<<(256 * 256 + 255) / 256, 256>>>(W1, w1h, w1l, 256, 256);
    wt_split_kernel<<<(512 * 256 + 255) / 256, 256>>>(W2, w2h, w2l, 512, 256);

    // mma.sync GEMMs (grid: x = N/128 = 2, y = M/128)
    gemm_mma_kernel<256><<<dim3(2, NQ / 128), 256>>>(a1h, a1l, w1h, w1l, b1, out);
    gemm_mma_kernel<512><<<dim3(2, NP / 128), 256>>>(a2h, a2l, w2h, w2l, b2, f2pre);

    // BN stats (deterministic)
    colstats_partial_kernel<<<NQ / 64, 256>>>(out, ps1, pq1);
    colstats_partial_kernel<<<NP / 64, 256>>>(f2pre, ps2, pq2);
    colstats_final_kernel<<<256, 128>>>(ps1, pq1, NQ / 64, 1.f / (float)NQ, mean1, rstd1);
    colstats_final_kernel<<<256, 128>>>(ps2, pq2, NP / 64, 1.f / (float)NP, mean2, rstd2);

    // Spatial grid
    grid_zero_kernel<<<64, 256>>>();
    grid_count_kernel<<<64, 256>>>(p2);
    grid_scan_kernel<<<4, 1024>>>();
    grid_scatter_kernel<<<64, 256>>>(p2);
    grid_sortfix_kernel<<<64, 256>>>();

    // KNN  (smem: points 64KB + cellStart 16KB + ids 16KB)
    size_t sm = N2C * sizeof(float4) + (NCELL + 16) * sizeof(int) + N2C * sizeof(int);
    cudaFuncSetAttribute(knn_kernel, cudaFuncAttributeMaxDynamicSharedMemorySize, (int)sm);
    knn_kernel<<<256, 256, sm>>>(p1);

    // Fused epilogue
    final_kernel<<<NQ, 256>>>(out, ga1, be1, ga2, be2);
}

// round 5
// speedup vs baseline: 1.6648x; 1.1581x over previous
#include <cuda_runtime.h>
#include <cuda_bf16.h>
#include <cstdint>

// Problem constants
#define CB      4          // batches
#define N1C     16384      // queries per batch
#define N2C     4096       // points per batch
#define NQ      (CB*N1C)   // 65536
#define NP      (CB*N2C)   // 16384
#define COUTC   256
#define GRIDG   16
#define NCELL   (GRIDG*GRIDG*GRIDG)  // 4096

__device__ __forceinline__ uint32_t smem_to_u32(const void* smem_ptr) {
    uint32_t addr;
    asm("{ .reg .u64 tmp; cvta.to.shared.u64 tmp, %1; cvt.u32.u64 %0, tmp; }"
        : "=r"(addr) : "l"(smem_ptr));
    return addr;
}
__device__ __forceinline__ void ldm_x4(uint32_t* r, uint32_t addr) {
    asm volatile("ldmatrix.sync.aligned.m8n8.x4.shared.b16 {%0,%1,%2,%3}, [%4];"
        : "=r"(r[0]), "=r"(r[1]), "=r"(r[2]), "=r"(r[3]) : "r"(addr));
}
__device__ __forceinline__ void ldm_x2(uint32_t* r, uint32_t addr) {
    asm volatile("ldmatrix.sync.aligned.m8n8.x2.shared.b16 {%0,%1}, [%2];"
        : "=r"(r[0]), "=r"(r[1]) : "r"(addr));
}
__device__ __forceinline__ void mma_bf16(float* c, const uint32_t* a, const uint32_t* b) {
    asm volatile("mma.sync.aligned.m16n8k16.row.col.f32.bf16.bf16.f32 "
        "{%0,%1,%2,%3}, {%4,%5,%6,%7}, {%8,%9}, {%0,%1,%2,%3};"
        : "+f"(c[0]), "+f"(c[1]), "+f"(c[2]), "+f"(c[3])
        : "r"(a[0]), "r"(a[1]), "r"(a[2]), "r"(a[3]), "r"(b[0]), "r"(b[1]));
}

// ---------------- device scratch (static — no allocation allowed) ------------
__device__ float  g_f2pre[NP * COUTC];         // 16 MB pre-activation of branch 2
__device__ __nv_bfloat16 g_W1h[256 * 256];     // transposed [N][K]
__device__ __nv_bfloat16 g_W1l[256 * 256];
__device__ __nv_bfloat16 g_W2h[256 * 512];
__device__ __nv_bfloat16 g_W2l[256 * 512];
__device__ float  g_psum1[512 * COUTC];
__device__ float  g_psq1 [512 * COUTC];
__device__ float  g_psum2[128 * COUTC];
__device__ float  g_psq2 [128 * COUTC];
__device__ float  g_mean1[COUTC], g_rstd1[COUTC];
__device__ float  g_mean2[COUTC], g_rstd2[COUTC];
__device__ int    g_cnt[CB * NCELL];
__device__ int    g_cellStart[CB * (NCELL + 1)];
__device__ int    g_cellPtr[CB * NCELL];
__device__ float4 g_sortedPts[CB * N2C];       // x,y,z,|p|^2  (cell-sorted)
__device__ int    g_sortedIdx[CB * N2C];       // original row index (global)
__device__ int    g_qcnt[CB * NCELL];
__device__ int    g_qptr[CB * NCELL];
__device__ float4 g_sortedQ[NQ];               // x,y,z,|q|^2  (cell-sorted queries)
__device__ int    g_sortedQid[NQ];
__device__ int    g_knnIdx[NQ * 3];
__device__ float  g_knnW [NQ * 3];

// transpose W[K][N] -> WT[N][K], with hi/lo split (small matrices)
__global__ __launch_bounds__(256) void wt_split_kernel(
    const float* __restrict__ W, __nv_bfloat16* __restrict__ th,
    __nv_bfloat16* __restrict__ tl, int K, int N)
{
    int i = blockIdx.x * 256 + threadIdx.x;
    if (i >= K * N) return;
    int k = i / N, n = i % N;
    float x = W[i];
    __nv_bfloat16 h = __float2bfloat16_rn(x);
    th[n * K + k] = h;
    tl[n * K + k] = __float2bfloat16_rn(x - __bfloat162float(h));
}

// ---------------- mma.sync bf16x3 GEMM with fused split + BN partials --------
// C[M,256] = A[M,K](fp32) @ WT[256,K]^T + bias.   D += Ah*Bh + Ah*Bl + Al*Bh.
// Block 128x128, BK=32, 8 warps (2m x 4n), warp tile 64x32 (4x4 m16n8k16).
// Register-prefetch pipelined; epilogue also emits per-block column sum/sumsq.
#define PITCH 40   // bf16 elements per smem row (80B — conflict-free ldmatrix)

template<int K>
__global__ __launch_bounds__(256) void gemm_mma_kernel(
    const float* __restrict__ A,
    const __nv_bfloat16* __restrict__ Bh, const __nv_bfloat16* __restrict__ Bl,
    const float* __restrict__ bias, float* __restrict__ C,
    float* __restrict__ ps, float* __restrict__ pq)
{
    __shared__ __nv_bfloat16 sAh[128 * PITCH], sAl[128 * PITCH];
    __shared__ __nv_bfloat16 sBh[128 * PITCH], sBl[128 * PITCH];
    __shared__ float sS[8][32], sQ[8][32];

    const int tid = threadIdx.x, lane = tid & 31, wid = tid >> 5;
    const int wm = wid & 1, wn = wid >> 1;      // warp grid: 2 (m) x 4 (n)
    const int m0 = blockIdx.y * 128, n0 = blockIdx.x * 128;

    const uint32_t uAh = smem_to_u32(sAh), uAl = smem_to_u32(sAl);
    const uint32_t uBh = smem_to_u32(sBh), uBl = smem_to_u32(sBl);

    float acc[4][4][4];
#pragma unroll
    for (int i = 0; i < 4; i++)
#pragma unroll
        for (int j = 0; j < 4; j++)
#pragma unroll
            for (int k = 0; k < 4; k++) acc[i][j][k] = 0.f;

    // ldmatrix per-lane byte offsets (within a tile array)
    const uint32_t aoff = ((uint32_t)((wm * 64 + (lane & 15)) * PITCH + (lane >> 4) * 8)) * 2;
    const uint32_t boff = ((uint32_t)((wn * 32 + (lane & 7)) * PITCH + ((lane >> 3) & 1) * 8)) * 2;

    float4 ra[4];        // A: 128 rows x 32 fp32; fid=i*256+tid -> row=fid>>3, q=fid&7
    uint4  rbh[2], rbl[2]; // B: 128 rows x 32 bf16; fid=i*256+tid -> row=fid>>2, q=fid&3

    auto load_tiles = [&](int k0) {
#pragma unroll
        for (int i = 0; i < 4; i++) {
            int fid = i * 256 + tid, r = fid >> 3, q = fid & 7;
            ra[i] = *(const float4*)(A + (size_t)(m0 + r) * K + k0 + q * 4);
        }
#pragma unroll
        for (int i = 0; i < 2; i++) {
            int fid = i * 256 + tid, r = fid >> 2, q = fid & 3;
            size_t gb = (size_t)(n0 + r) * K + k0 + q * 8;
            rbh[i] = *(const uint4*)(Bh + gb);
            rbl[i] = *(const uint4*)(Bl + gb);
        }
    };
    auto store_tiles = [&]() {
#pragma unroll
        for (int i = 0; i < 4; i++) {
            int fid = i * 256 + tid, r = fid >> 3, q = fid & 7;
            float4 v = ra[i];
            __nv_bfloat16 h0 = __float2bfloat16_rn(v.x);
            __nv_bfloat16 h1 = __float2bfloat16_rn(v.y);
            __nv_bfloat16 h2 = __float2bfloat16_rn(v.z);
            __nv_bfloat16 h3 = __float2bfloat16_rn(v.w);
            __nv_bfloat16 l0 = __float2bfloat16_rn(v.x - __bfloat162float(h0));
            __nv_bfloat16 l1 = __float2bfloat16_rn(v.y - __bfloat162float(h1));
            __nv_bfloat16 l2 = __float2bfloat16_rn(v.z - __bfloat162float(h2));
            __nv_bfloat16 l3 = __float2bfloat16_rn(v.w - __bfloat162float(h3));
            int so = r * PITCH + q * 4;
            *(__nv_bfloat162*)(sAh + so)     = __nv_bfloat162(h0, h1);
            *(__nv_bfloat162*)(sAh + so + 2) = __nv_bfloat162(h2, h3);
            *(__nv_bfloat162*)(sAl + so)     = __nv_bfloat162(l0, l1);
            *(__nv_bfloat162*)(sAl + so + 2) = __nv_bfloat162(l2, l3);
        }
#pragma unroll
        for (int i = 0; i < 2; i++) {
            int fid = i * 256 + tid, r = fid >> 2, q = fid & 3;
            int so = r * PITCH + q * 8;
            *(uint4*)(sBh + so) = rbh[i];
            *(uint4*)(sBl + so) = rbl[i];
        }
    };

    load_tiles(0);
    const int NIT = K / 32;
    for (int kt = 0; kt < NIT; kt++) {
        store_tiles();
        __syncthreads();
        if (kt + 1 < NIT) load_tiles((kt + 1) * 32);

#pragma unroll
        for (int ks = 0; ks < 2; ks++) {
            uint32_t afh[4][4], afl[4][4], bfh[4][2], bfl[4][2];
#pragma unroll
            for (int mt = 0; mt < 4; mt++) {
                uint32_t o = aoff + (uint32_t)(mt * 16 * PITCH + ks * 16) * 2;
                ldm_x4(afh[mt], uAh + o);
                ldm_x4(afl[mt], uAl + o);
            }
#pragma unroll
            for (int nt = 0; nt < 4; nt++) {
                uint32_t o = boff + (uint32_t)(nt * 8 * PITCH + ks * 16) * 2;
                ldm_x2(bfh[nt], uBh + o);
                ldm_x2(bfl[nt], uBl + o);
            }
#pragma unroll
            for (int mt = 0; mt < 4; mt++)
#pragma unroll
                for (int nt = 0; nt < 4; nt++) {
                    mma_bf16(acc[mt][nt], afh[mt], bfh[nt]);
                    mma_bf16(acc[mt][nt], afh[mt], bfl[nt]);
                    mma_bf16(acc[mt][nt], afl[mt], bfh[nt]);
                }
        }
        __syncthreads();
    }

    // epilogue: bias add, store C, per-block column sum/sumsq
    const int tr = lane >> 2, tc = (lane & 3) * 2;
    const int rbase = m0 + wm * 64, cbase = n0 + wn * 32;
#pragma unroll
    for (int nt = 0; nt < 4; nt++) {
        int col = cbase + nt * 8 + tc;
        float bx = bias[col], by = bias[col + 1];
        float s0 = 0.f, s1 = 0.f, q0 = 0.f, q1 = 0.f;
#pragma unroll
        for (int mt = 0; mt < 4; mt++) {
            int row = rbase + mt * 16 + tr;
            float v0 = acc[mt][nt][0] + bx, v1 = acc[mt][nt][1] + by;
            float v2 = acc[mt][nt][2] + bx, v3 = acc[mt][nt][3] + by;
            *(float2*)(C + (size_t)row * 256 + col) = make_float2(v0, v1);
            *(float2*)(C + (size_t)(row + 8) * 256 + col) = make_float2(v2, v3);
            s0 += v0 + v2; s1 += v1 + v3;
            q0 = fmaf(v0, v0, q0); q0 = fmaf(v2, v2, q0);
            q1 = fmaf(v1, v1, q1); q1 = fmaf(v3, v3, q1);
        }
#pragma unroll
        for (int off = 4; off <= 16; off <<= 1) {
            s0 += __shfl_xor_sync(0xffffffff, s0, off);
            s1 += __shfl_xor_sync(0xffffffff, s1, off);
            q0 += __shfl_xor_sync(0xffffffff, q0, off);
            q1 += __shfl_xor_sync(0xffffffff, q1, off);
        }
        if (tr == 0) {
            int lc = nt * 8 + tc;
            sS[wid][lc] = s0; sS[wid][lc + 1] = s1;
            sQ[wid][lc] = q0; sQ[wid][lc + 1] = q1;
        }
    }
    __syncthreads();
    if (tid < 128) {
        int wn2 = tid >> 5, col = tid & 31;
        float s = sS[wn2 * 2][col] + sS[wn2 * 2 + 1][col];
        float q = sQ[wn2 * 2][col] + sQ[wn2 * 2 + 1][col];
        int gc = n0 + wn2 * 32 + col;
        ps[(size_t)blockIdx.y * 256 + gc] = s;
        pq[(size_t)blockIdx.y * 256 + gc] = q;
    }
}

// ---------------- BN stats final reduce (deterministic) ----------------------
__global__ __launch_bounds__(128) void colstats_final_kernel(
    const float* __restrict__ ps, const float* __restrict__ pq,
    int nch, float invR, float* __restrict__ mean, float* __restrict__ rstd)
{
    int c = blockIdx.x, t = threadIdx.x;
    float s = 0.f, q = 0.f;
    for (int i = t; i < nch; i += 128) { s += ps[i * COUTC + c]; q += pq[i * COUTC + c]; }
    __shared__ float ss[128], sq[128];
    ss[t] = s; sq[t] = q;
    __syncthreads();
    for (int o = 64; o > 0; o >>= 1) {
        if (t < o) { ss[t] += ss[t + o]; sq[t] += sq[t + o]; }
        __syncthreads();
    }
    if (t == 0) {
        float mu = ss[0] * invR;
        float var = sq[0] * invR - mu * mu;
        mean[c] = mu;
        rstd[c] = rsqrtf(var + 1e-5f);
    }
}

// ---------------- grid build ------------------------------------------------
__device__ __forceinline__ int cell_of(float x, float y, float z, int* cx, int* cy, int* cz)
{
    int ix = min(max((int)(x * 16.f), 0), 15);
    int iy = min(max((int)(y * 16.f), 0), 15);
    int iz = min(max((int)(z * 16.f), 0), 15);
    *cx = ix; *cy = iy; *cz = iz;
    return (iz << 8) + (iy << 4) + ix;
}

__global__ void grid_zero_kernel()
{
    int i = blockIdx.x * 256 + threadIdx.x;
    if (i < CB * NCELL) { g_cnt[i] = 0; g_qcnt[i] = 0; }
}

__global__ void grid_count_kernel(const float* __restrict__ p2)
{
    int i = blockIdx.x * 256 + threadIdx.x;
    if (i >= NP) return;
    int b = i >> 12;
    float x = p2[i * 3], y = p2[i * 3 + 1], z = p2[i * 3 + 2];
    int cx, cy, cz;
    int cell = cell_of(x, y, z, &cx, &cy, &cz);
    atomicAdd(&g_cnt[b * NCELL + cell], 1);
}

__global__ void q_count_kernel(const float* __restrict__ p1)
{
    int i = blockIdx.x * 256 + threadIdx.x;
    if (i >= NQ) return;
    int b = i >> 14;
    float x = p1[i * 3], y = p1[i * 3 + 1], z = p1[i * 3 + 2];
    int cx, cy, cz;
    int cell = cell_of(x, y, z, &cx, &cy, &cz);
    atomicAdd(&g_qcnt[b * NCELL + cell], 1);
}

// scan: per batch, 4 cells/thread; writes exclusive starts into start/ptr
__global__ __launch_bounds__(1024) void grid_scan_kernel(
    const int* __restrict__ cnt, int* __restrict__ start, int* __restrict__ ptr)
{
    __shared__ int ts[1024];
    int b = blockIdx.x, t = threadIdx.x;
    int v0 = cnt[b * NCELL + t * 4 + 0];
    int v1 = cnt[b * NCELL + t * 4 + 1];
    int v2 = cnt[b * NCELL + t * 4 + 2];
    int v3 = cnt[b * NCELL + t * 4 + 3];
    int loc = v0 + v1 + v2 + v3;
    ts[t] = loc;
    __syncthreads();
    for (int off = 1; off < 1024; off <<= 1) {
        int add = (t >= off) ? ts[t - off] : 0;
        __syncthreads();
        ts[t] += add;
        __syncthreads();
    }
    int p = ts[t] - loc;
    int base = b * (NCELL + 1);
    if (start) { 
        start[base + t * 4 + 0] = p;
        start[base + t * 4 + 1] = p + v0;
        start[base + t * 4 + 2] = p + v0 + v1;
        start[base + t * 4 + 3] = p + v0 + v1 + v2;
        if (t == 1023) start[base + NCELL] = ts[1023];
    }
    ptr[b * NCELL + t * 4 + 0] = p;         p += v0;
    ptr[b * NCELL + t * 4 + 1] = p;         p += v1;
    ptr[b * NCELL + t * 4 + 2] = p;         p += v2;
    ptr[b * NCELL + t * 4 + 3] = p;
}

__global__ void grid_scatter_kernel(const float* __restrict__ p2)
{
    int i = blockIdx.x * 256 + threadIdx.x;
    if (i >= NP) return;
    int b = i >> 12;
    float x = p2[i * 3], y = p2[i * 3 + 1], z = p2[i * 3 + 2];
    // |p|^2 with the reference's rounding: fl(fl(x*x)+fl(y*y))+fl(z*z)
    float pp = __fadd_rn(__fadd_rn(__fmul_rn(x, x), __fmul_rn(y, y)), __fmul_rn(z, z));
    int cx, cy, cz;
    int cell = cell_of(x, y, z, &cx, &cy, &cz);
    int pos = atomicAdd(&g_cellPtr[b * NCELL + cell], 1);
    g_sortedPts[b * N2C + pos] = make_float4(x, y, z, pp);
    g_sortedIdx[b * N2C + pos] = i;   // original global row
}

__global__ void q_scatter_kernel(const float* __restrict__ p1)
{
    int i = blockIdx.x * 256 + threadIdx.x;
    if (i >= NQ) return;
    int b = i >> 14;
    float x = p1[i * 3], y = p1[i * 3 + 1], z = p1[i * 3 + 2];
    float qq = __fadd_rn(__fadd_rn(__fmul_rn(x, x), __fmul_rn(y, y)), __fmul_rn(z, z));
    int cx, cy, cz;
    int cell = cell_of(x, y, z, &cx, &cy, &cz);
    int pos = atomicAdd(&g_qptr[b * NCELL + cell], 1);
    g_sortedQ[b * N1C + pos] = make_float4(x, y, z, qq);
    g_sortedQid[b * N1C + pos] = i;
}

// Make within-cell point order deterministic (ascending original index).
__global__ void grid_sortfix_kernel()
{
    int t = blockIdx.x * 256 + threadIdx.x;
    if (t >= CB * NCELL) return;
    int b = t >> 12, cell = t & 4095;
    int s = g_cellStart[b * (NCELL + 1) + cell];
    int e = g_cellStart[b * (NCELL + 1) + cell + 1];
    int base = b * N2C;
    for (int a = s + 1; a < e; a++) {
        int ia = g_sortedIdx[base + a];
        float4 pa = g_sortedPts[base + a];
        int k = a - 1;
        while (k >= s && g_sortedIdx[base + k] > ia) {
            g_sortedIdx[base + k + 1] = g_sortedIdx[base + k];
            g_sortedPts[base + k + 1] = g_sortedPts[base + k];
            k--;
        }
        g_sortedIdx[base + k + 1] = ia;
        g_sortedPts[base + k + 1] = pa;
    }
}

// ---------------- KNN (K=3) via grid ring expansion, cell-sorted queries -----
// Exactly emulates reference rounding (rn intrinsics, contraction-proof).
__global__ __launch_bounds__(256) void knn_kernel()
{
    extern __shared__ unsigned char smraw[];
    float4* sp = (float4*)smraw;                                  // 4096 float4
    int* cs  = (int*)(smraw + N2C * sizeof(float4));              // 4097 ints
    int* sid = (int*)(smraw + N2C * sizeof(float4) + (NCELL + 16) * sizeof(int)); // 4096 ints

    int pos = blockIdx.x * 256 + threadIdx.x;
    int batch = pos >> 14;
    for (int i = threadIdx.x; i < N2C; i += 256) {
        sp[i]  = g_sortedPts[batch * N2C + i];
        sid[i] = g_sortedIdx[batch * N2C + i];
    }
    for (int i = threadIdx.x; i < NCELL + 1; i += 256)
        cs[i] = g_cellStart[batch * (NCELL + 1) + i];
    __syncthreads();

    float4 qv = g_sortedQ[pos];
    int qid = g_sortedQid[pos];
    float qx = qv.x, qy = qv.y, qz = qv.z, qq = qv.w;

    int cx, cy, cz;
    (void)cell_of(qx, qy, qz, &cx, &cy, &cz);

    float b0 = 3.4e38f, b1 = 3.4e38f, b2 = 3.4e38f;
    int i0 = 0x7fffffff, i1 = 0x7fffffff, i2 = 0x7fffffff;

    auto proc = [&](int s, int e) {
        for (int j = s; j < e; j++) {
            float4 p = sp[j];
            int oi = sid[j];
            float dot = fmaf(qz, p.z, fmaf(qy, p.y, __fmul_rn(qx, p.x)));
            float d2 = __fsub_rn(__fadd_rn(qq, p.w), __fmul_rn(2.0f, dot));
            bool lt2 = (d2 < b2) || (d2 == b2 && oi < i2);
            if (lt2) {
                bool lt1 = (d2 < b1) || (d2 == b1 && oi < i1);
                if (lt1) {
                    b2 = b1; i2 = i1;
                    bool lt0 = (d2 < b0) || (d2 == b0 && oi < i0);
                    if (lt0) { b1 = b0; i1 = i0; b0 = d2; i0 = oi; }
                    else     { b1 = d2; i1 = oi; }
                } else { b2 = d2; i2 = oi; }
            }
        }
    };

    const float h = 0.0625f;
    int rmax = max(max(cx, 15 - cx), max(max(cy, 15 - cy), max(cz, 15 - cz)));
    for (int r = 0; r <= rmax; r++) {
        if (r > 0) {
            float bnd = (float)(r - 1) * h;   // all unvisited points are >= bnd away
            if (b2 <= bnd * bnd - 1e-6f) break;   // slack for fp32 rounding of d2
        }
        int zlo = max(cz - r, 0), zhi = min(cz + r, 15);
        for (int z = zlo; z <= zhi; z++) {
            bool ze = (z == cz - r) || (z == cz + r);
            int ylo = max(cy - r, 0), yhi = min(cy + r, 15);
            for (int y = ylo; y <= yhi; y++) {
                bool ye = (y == cy - r) || (y == cy + r);
                int rb = (z << 8) + (y << 4);
                if (ze || ye) {
                    int xlo = max(cx - r, 0), xhi = min(cx + r, 15);
                    proc(cs[rb + xlo], cs[rb + xhi + 1]);   // contiguous x-span
                } else {
                    if (cx - r >= 0) proc(cs[rb + cx - r], cs[rb + cx - r + 1]);
                    if (cx + r <= 15) proc(cs[rb + cx + r], cs[rb + cx + r + 1]);
                }
            }
        }
    }

    float d0 = fmaxf(b0, 0.f), d1 = fmaxf(b1, 0.f), d2c = fmaxf(b2, 0.f);
    float r0 = __fdiv_rn(1.0f, __fadd_rn(d0, 1e-8f));
    float r1 = __fdiv_rn(1.0f, __fadd_rn(d1, 1e-8f));
    float r2 = __fdiv_rn(1.0f, __fadd_rn(d2c, 1e-8f));
    float sum = __fadd_rn(__fadd_rn(r0, r1), r2);

    g_knnIdx[qid * 3 + 0] = i0;
    g_knnIdx[qid * 3 + 1] = i1;
    g_knnIdx[qid * 3 + 2] = i2;
    g_knnW[qid * 3 + 0] = __fdiv_rn(r0, sum);
    g_knnW[qid * 3 + 1] = __fdiv_rn(r1, sum);
    g_knnW[qid * 3 + 2] = __fdiv_rn(r2, sum);
}

// ---------------- final: BN+relu both branches, gather, weighted add ---------
__global__ __launch_bounds__(256) void final_kernel(
    float* io,
    const float* __restrict__ ga1, const float* __restrict__ be1,
    const float* __restrict__ ga2, const float* __restrict__ be2)
{
    int row = blockIdx.x, c = threadIdx.x;
    __shared__ int si[3];
    __shared__ float sw[3];
    if (c < 3) { si[c] = g_knnIdx[row * 3 + c]; sw[c] = g_knnW[row * 3 + c]; }
    __syncthreads();

    float x = io[(size_t)row * COUTC + c];
    float v1 = fmaxf(ga1[c] * (x - g_mean1[c]) * g_rstd1[c] + be1[c], 0.f);

    float acc = 0.f;
#pragma unroll
    for (int k = 0; k < 3; k++) {
        float y = g_f2pre[(size_t)si[k] * COUTC + c];
        float v = fmaxf(ga2[c] * (y - g_mean2[c]) * g_rstd2[c] + be2[c], 0.f);
        acc = fmaf(sw[k], v, acc);
    }
    io[(size_t)row * COUTC + c] = v1 + acc;
}

// ---------------- launch ----------------------------------------------------
extern "C" void kernel_launch(void* const* d_in, const int* in_sizes, int n_in,
                              void* d_out, int out_size)
{
    const float* p1  = (const float*)d_in[0];
    const float* f1  = (const float*)d_in[1];
    const float* p2  = (const float*)d_in[2];
    const float* f2  = (const float*)d_in[3];
    const float* W1  = (const float*)d_in[4];
    const float* b1  = (const float*)d_in[5];
    const float* ga1 = (const float*)d_in[6];
    const float* be1 = (const float*)d_in[7];
    const float* W2  = (const float*)d_in[8];
    const float* b2  = (const float*)d_in[9];
    const float* ga2 = (const float*)d_in[10];
    const float* be2 = (const float*)d_in[11];
    float* out = (float*)d_out;

    float *f2pre, *ps1, *pq1, *ps2, *pq2, *mean1, *rstd1, *mean2, *rstd2;
    __nv_bfloat16 *w1h, *w1l, *w2h, *w2l;
    int *cnt, *cellStart, *cellPtr, *qcnt, *qptr;
    cudaGetSymbolAddress((void**)&f2pre, g_f2pre);
    cudaGetSymbolAddress((void**)&ps1, g_psum1);
    cudaGetSymbolAddress((void**)&pq1, g_psq1);
    cudaGetSymbolAddress((void**)&ps2, g_psum2);
    cudaGetSymbolAddress((void**)&pq2, g_psq2);
    cudaGetSymbolAddress((void**)&mean1, g_mean1);
    cudaGetSymbolAddress((void**)&rstd1, g_rstd1);
    cudaGetSymbolAddress((void**)&mean2, g_mean2);
    cudaGetSymbolAddress((void**)&rstd2, g_rstd2);
    cudaGetSymbolAddress((void**)&w1h, g_W1h);
    cudaGetSymbolAddress((void**)&w1l, g_W1l);
    cudaGetSymbolAddress((void**)&w2h, g_W2h);
    cudaGetSymbolAddress((void**)&w2l, g_W2l);
    cudaGetSymbolAddress((void**)&cnt, g_cnt);
    cudaGetSymbolAddress((void**)&cellStart, g_cellStart);
    cudaGetSymbolAddress((void**)&cellPtr, g_cellPtr);
    cudaGetSymbolAddress((void**)&qcnt, g_qcnt);
    cudaGetSymbolAddress((void**)&qptr, g_qptr);

    // weight transpose + hi/lo split
    wt_split_kernel<<<(256 * 256 + 255) / 256, 256>>>(W1, w1h, w1l, 256, 256);
    wt_split_kernel<<<(512 * 256 + 255) / 256, 256>>>(W2, w2h, w2l, 512, 256);

    // spatial grids (points + queries) — independent of GEMMs
    grid_zero_kernel<<<64, 256>>>();
    grid_count_kernel<<<64, 256>>>(p2);
    q_count_kernel<<<256, 256>>>(p1);
    grid_scan_kernel<<<4, 1024>>>(cnt, cellStart, cellPtr);
    grid_scan_kernel<<<4, 1024>>>(qcnt, (int*)nullptr, qptr);
    grid_scatter_kernel<<<64, 256>>>(p2);
    q_scatter_kernel<<<256, 256>>>(p1);
    grid_sortfix_kernel<<<64, 256>>>();

    // GEMMs with fused fp32->bf16x3 conversion and fused BN partial stats
    gemm_mma_kernel<256><<<dim3(2, NQ / 128), 256>>>(f1, w1h, w1l, b1, out, ps1, pq1);
    gemm_mma_kernel<512><<<dim3(2, NP / 128), 256>>>(f2, w2h, w2l, b2, f2pre, ps2, pq2);

    // BN stats final
    colstats_final_kernel<<<256, 128>>>(ps1, pq1, NQ / 128, 1.f / (float)NQ, mean1, rstd1);
    colstats_final_kernel<<<256, 128>>>(ps2, pq2, NP / 128, 1.f / (float)NP, mean2, rstd2);

    // KNN  (smem: points 64KB + cellStart 16KB + ids 16KB)
    size_t sm = N2C * sizeof(float4) + (NCELL + 16) * sizeof(int) + N2C * sizeof(int);
    cudaFuncSetAttribute(knn_kernel, cudaFuncAttributeMaxDynamicSharedMemorySize, (int)sm);
    knn_kernel<<<256, 256, sm>>>();

    // Fused epilogue
    final_kernel<<<NQ, 256>>>(out, ga1, be1, ga2, be2);
}

// round 6
// speedup vs baseline: 1.8542x; 1.1138x over previous
#include <cuda_runtime.h>
#include <cuda_bf16.h>
#include <cstdint>

// Problem constants
#define CB      4          // batches
#define N1C     16384      // queries per batch
#define N2C     4096       // points per batch
#define NQ      (CB*N1C)   // 65536
#define NP      (CB*N2C)   // 16384
#define COUTC   256
#define GRIDG   16
#define NCELL   (GRIDG*GRIDG*GRIDG)  // 4096

__device__ __forceinline__ uint32_t smem_to_u32(const void* smem_ptr) {
    uint32_t addr;
    asm("{ .reg .u64 tmp; cvta.to.shared.u64 tmp, %1; cvt.u32.u64 %0, tmp; }"
        : "=r"(addr) : "l"(smem_ptr));
    return addr;
}
__device__ __forceinline__ void ldm_x4(uint32_t* r, uint32_t addr) {
    asm volatile("ldmatrix.sync.aligned.m8n8.x4.shared.b16 {%0,%1,%2,%3}, [%4];"
        : "=r"(r[0]), "=r"(r[1]), "=r"(r[2]), "=r"(r[3]) : "r"(addr));
}
__device__ __forceinline__ void ldm_x2(uint32_t* r, uint32_t addr) {
    asm volatile("ldmatrix.sync.aligned.m8n8.x2.shared.b16 {%0,%1}, [%2];"
        : "=r"(r[0]), "=r"(r[1]) : "r"(addr));
}
__device__ __forceinline__ void mma_bf16(float* c, const uint32_t* a, const uint32_t* b) {
    asm volatile("mma.sync.aligned.m16n8k16.row.col.f32.bf16.bf16.f32 "
        "{%0,%1,%2,%3}, {%4,%5,%6,%7}, {%8,%9}, {%0,%1,%2,%3};"
        : "+f"(c[0]), "+f"(c[1]), "+f"(c[2]), "+f"(c[3])
        : "r"(a[0]), "r"(a[1]), "r"(a[2]), "r"(a[3]), "r"(b[0]), "r"(b[1]));
}

// ---------------- device scratch (static — no allocation allowed) ------------
__device__ float  g_f2pre[NP * COUTC];         // 16 MB pre-activation of branch 2
__device__ __nv_bfloat16 g_W1h[256 * 256];     // transposed [N][K]
__device__ __nv_bfloat16 g_W1l[256 * 256];
__device__ __nv_bfloat16 g_W2h[256 * 512];
__device__ __nv_bfloat16 g_W2l[256 * 512];
__device__ float  g_psum1[512 * COUTC];
__device__ float  g_psq1 [512 * COUTC];
__device__ float  g_psum2[128 * COUTC];
__device__ float  g_psq2 [128 * COUTC];
__device__ float  g_mean1[COUTC], g_rstd1[COUTC];
__device__ float  g_mean2[COUTC], g_rstd2[COUTC];
__device__ int    g_cnt[CB * NCELL];
__device__ int    g_cellStart[CB * (NCELL + 1)];
__device__ int    g_cellPtr[CB * NCELL];
__device__ float4 g_sortedPts[CB * N2C];       // x,y,z,|p|^2  (cell-sorted)
__device__ int    g_sortedIdx[CB * N2C];       // original row index (global)
__device__ int    g_qcnt[CB * NCELL];
__device__ int    g_qptr[CB * NCELL];
__device__ float4 g_sortedQ[NQ];               // x,y,z,|q|^2  (cell-sorted queries)
__device__ int    g_sortedQid[NQ];
__device__ int    g_knnIdx[NQ * 3];
__device__ float  g_knnW [NQ * 3];

// Both weight transposes + hi/lo splits in one launch.
// i < 256*256 -> W1, else W2.
__global__ __launch_bounds__(256) void wt_split_all_kernel(
    const float* __restrict__ W1, const float* __restrict__ W2)
{
    int i = blockIdx.x * 256 + threadIdx.x;
    if (i < 256 * 256) {
        int k = i >> 8, n = i & 255;
        float x = W1[i];
        __nv_bfloat16 h = __float2bfloat16_rn(x);
        g_W1h[n * 256 + k] = h;
        g_W1l[n * 256 + k] = __float2bfloat16_rn(x - __bfloat162float(h));
    } else {
        int j = i - 256 * 256;
        if (j >= 512 * 256) return;
        int k = j >> 8, n = j & 255;
        float x = W2[j];
        __nv_bfloat16 h = __float2bfloat16_rn(x);
        g_W2h[n * 512 + k] = h;
        g_W2l[n * 512 + k] = __float2bfloat16_rn(x - __bfloat162float(h));
    }
}

// ---------------- mma.sync bf16x3 GEMM with fused split + BN partials --------
// C[M,256] = A[M,K](fp32) @ WT[256,K]^T + bias.   D += Ah*Bh + Ah*Bl + Al*Bh.
// Block 128x128, BK=32, 8 warps (2m x 4n), warp tile 64x32 (4x4 m16n8k16).
// Register-prefetch pipelined; epilogue also emits per-block column sum/sumsq.
#define PITCH 40   // bf16 elements per smem row (80B — conflict-free ldmatrix)

template<int K>
__global__ __launch_bounds__(256, 2) void gemm_mma_kernel(
    const float* __restrict__ A,
    const __nv_bfloat16* __restrict__ Bh, const __nv_bfloat16* __restrict__ Bl,
    const float* __restrict__ bias, float* __restrict__ C,
    float* __restrict__ ps, float* __restrict__ pq)
{
    __shared__ __nv_bfloat16 sAh[128 * PITCH], sAl[128 * PITCH];
    __shared__ __nv_bfloat16 sBh[128 * PITCH], sBl[128 * PITCH];
    __shared__ float sS[8][32], sQ[8][32];

    const int tid = threadIdx.x, lane = tid & 31, wid = tid >> 5;
    const int wm = wid & 1, wn = wid >> 1;      // warp grid: 2 (m) x 4 (n)
    const int m0 = blockIdx.y * 128, n0 = blockIdx.x * 128;

    const uint32_t uAh = smem_to_u32(sAh), uAl = smem_to_u32(sAl);
    const uint32_t uBh = smem_to_u32(sBh), uBl = smem_to_u32(sBl);

    float acc[4][4][4];
#pragma unroll
    for (int i = 0; i < 4; i++)
#pragma unroll
        for (int j = 0; j < 4; j++)
#pragma unroll
            for (int k = 0; k < 4; k++) acc[i][j][k] = 0.f;

    // ldmatrix per-lane byte offsets (within a tile array)
    const uint32_t aoff = ((uint32_t)((wm * 64 + (lane & 15)) * PITCH + (lane >> 4) * 8)) * 2;
    const uint32_t boff = ((uint32_t)((wn * 32 + (lane & 7)) * PITCH + ((lane >> 3) & 1) * 8)) * 2;

    float4 ra[4];          // A: 128 rows x 32 fp32
    uint4  rbh[2], rbl[2]; // B: 128 rows x 32 bf16

    auto load_tiles = [&](int k0) {
#pragma unroll
        for (int i = 0; i < 4; i++) {
            int fid = i * 256 + tid, r = fid >> 3, q = fid & 7;
            ra[i] = *(const float4*)(A + (size_t)(m0 + r) * K + k0 + q * 4);
        }
#pragma unroll
        for (int i = 0; i < 2; i++) {
            int fid = i * 256 + tid, r = fid >> 2, q = fid & 3;
            size_t gb = (size_t)(n0 + r) * K + k0 + q * 8;
            rbh[i] = *(const uint4*)(Bh + gb);
            rbl[i] = *(const uint4*)(Bl + gb);
        }
    };
    auto store_tiles = [&]() {
#pragma unroll
        for (int i = 0; i < 4; i++) {
            int fid = i * 256 + tid, r = fid >> 3, q = fid & 7;
            float4 v = ra[i];
            __nv_bfloat16 h0 = __float2bfloat16_rn(v.x);
            __nv_bfloat16 h1 = __float2bfloat16_rn(v.y);
            __nv_bfloat16 h2 = __float2bfloat16_rn(v.z);
            __nv_bfloat16 h3 = __float2bfloat16_rn(v.w);
            __nv_bfloat16 l0 = __float2bfloat16_rn(v.x - __bfloat162float(h0));
            __nv_bfloat16 l1 = __float2bfloat16_rn(v.y - __bfloat162float(h1));
            __nv_bfloat16 l2 = __float2bfloat16_rn(v.z - __bfloat162float(h2));
            __nv_bfloat16 l3 = __float2bfloat16_rn(v.w - __bfloat162float(h3));
            int so = r * PITCH + q * 4;
            *(__nv_bfloat162*)(sAh + so)     = __nv_bfloat162(h0, h1);
            *(__nv_bfloat162*)(sAh + so + 2) = __nv_bfloat162(h2, h3);
            *(__nv_bfloat162*)(sAl + so)     = __nv_bfloat162(l0, l1);
            *(__nv_bfloat162*)(sAl + so + 2) = __nv_bfloat162(l2, l3);
        }
#pragma unroll
        for (int i = 0; i < 2; i++) {
            int fid = i * 256 + tid, r = fid >> 2, q = fid & 3;
            int so = r * PITCH + q * 8;
            *(uint4*)(sBh + so) = rbh[i];
            *(uint4*)(sBl + so) = rbl[i];
        }
    };

    load_tiles(0);
    const int NIT = K / 32;
    for (int kt = 0; kt < NIT; kt++) {
        store_tiles();
        __syncthreads();
        if (kt + 1 < NIT) load_tiles((kt + 1) * 32);

#pragma unroll
        for (int ks = 0; ks < 2; ks++) {
            uint32_t afh[4][4], afl[4][4], bfh[4][2], bfl[4][2];
#pragma unroll
            for (int mt = 0; mt < 4; mt++) {
                uint32_t o = aoff + (uint32_t)(mt * 16 * PITCH + ks * 16) * 2;
                ldm_x4(afh[mt], uAh + o);
                ldm_x4(afl[mt], uAl + o);
            }
#pragma unroll
            for (int nt = 0; nt < 4; nt++) {
                uint32_t o = boff + (uint32_t)(nt * 8 * PITCH + ks * 16) * 2;
                ldm_x2(bfh[nt], uBh + o);
                ldm_x2(bfl[nt], uBl + o);
            }
#pragma unroll
            for (int mt = 0; mt < 4; mt++)
#pragma unroll
                for (int nt = 0; nt < 4; nt++) {
                    mma_bf16(acc[mt][nt], afh[mt], bfh[nt]);
                    mma_bf16(acc[mt][nt], afh[mt], bfl[nt]);
                    mma_bf16(acc[mt][nt], afl[mt], bfh[nt]);
                }
        }
        __syncthreads();
    }

    // epilogue: bias add, store C, per-block column sum/sumsq
    const int tr = lane >> 2, tc = (lane & 3) * 2;
    const int rbase = m0 + wm * 64, cbase = n0 + wn * 32;
#pragma unroll
    for (int nt = 0; nt < 4; nt++) {
        int col = cbase + nt * 8 + tc;
        float bx = bias[col], by = bias[col + 1];
        float s0 = 0.f, s1 = 0.f, q0 = 0.f, q1 = 0.f;
#pragma unroll
        for (int mt = 0; mt < 4; mt++) {
            int row = rbase + mt * 16 + tr;
            float v0 = acc[mt][nt][0] + bx, v1 = acc[mt][nt][1] + by;
            float v2 = acc[mt][nt][2] + bx, v3 = acc[mt][nt][3] + by;
            *(float2*)(C + (size_t)row * 256 + col) = make_float2(v0, v1);
            *(float2*)(C + (size_t)(row + 8) * 256 + col) = make_float2(v2, v3);
            s0 += v0 + v2; s1 += v1 + v3;
            q0 = fmaf(v0, v0, q0); q0 = fmaf(v2, v2, q0);
            q1 = fmaf(v1, v1, q1); q1 = fmaf(v3, v3, q1);
        }
#pragma unroll
        for (int off = 4; off <= 16; off <<= 1) {
            s0 += __shfl_xor_sync(0xffffffff, s0, off);
            s1 += __shfl_xor_sync(0xffffffff, s1, off);
            q0 += __shfl_xor_sync(0xffffffff, q0, off);
            q1 += __shfl_xor_sync(0xffffffff, q1, off);
        }
        if (tr == 0) {
            int lc = nt * 8 + tc;
            sS[wid][lc] = s0; sS[wid][lc + 1] = s1;
            sQ[wid][lc] = q0; sQ[wid][lc + 1] = q1;
        }
    }
    __syncthreads();
    if (tid < 128) {
        int wn2 = tid >> 5, col = tid & 31;
        float s = sS[wn2 * 2][col] + sS[wn2 * 2 + 1][col];
        float q = sQ[wn2 * 2][col] + sQ[wn2 * 2 + 1][col];
        int gc = n0 + wn2 * 32 + col;
        ps[(size_t)blockIdx.y * 256 + gc] = s;
        pq[(size_t)blockIdx.y * 256 + gc] = q;
    }
}

// ---------------- BN stats final reduce, both sets in one launch -------------
__global__ __launch_bounds__(128) void colstats_final_all_kernel()
{
    int bc = blockIdx.x, t = threadIdx.x;
    const float* ps; const float* pq; float* mean; float* rstd;
    int nch; float invR; int c;
    if (bc < 256) {
        c = bc; ps = g_psum1; pq = g_psq1; mean = g_mean1; rstd = g_rstd1;
        nch = NQ / 128; invR = 1.f / (float)NQ;
    } else {
        c = bc - 256; ps = g_psum2; pq = g_psq2; mean = g_mean2; rstd = g_rstd2;
        nch = NP / 128; invR = 1.f / (float)NP;
    }
    float s = 0.f, q = 0.f;
    for (int i = t; i < nch; i += 128) { s += ps[i * COUTC + c]; q += pq[i * COUTC + c]; }
    __shared__ float ss[128], sq[128];
    ss[t] = s; sq[t] = q;
    __syncthreads();
    for (int o = 64; o > 0; o >>= 1) {
        if (t < o) { ss[t] += ss[t + o]; sq[t] += sq[t + o]; }
        __syncthreads();
    }
    if (t == 0) {
        float mu = ss[0] * invR;
        float var = sq[0] * invR - mu * mu;
        mean[c] = mu;
        rstd[c] = rsqrtf(var + 1e-5f);
    }
}

// ---------------- grid build ------------------------------------------------
__device__ __forceinline__ int cell_of(float x, float y, float z, int* cx, int* cy, int* cz)
{
    int ix = min(max((int)(x * 16.f), 0), 15);
    int iy = min(max((int)(y * 16.f), 0), 15);
    int iz = min(max((int)(z * 16.f), 0), 15);
    *cx = ix; *cy = iy; *cz = iz;
    return (iz << 8) + (iy << 4) + ix;
}

__global__ void grid_zero_kernel()
{
    int i = blockIdx.x * 256 + threadIdx.x;
    if (i < CB * NCELL) { g_cnt[i] = 0; g_qcnt[i] = 0; }
}

// counts for points (blocks 0..63) and queries (blocks 64..319)
__global__ void count_all_kernel(const float* __restrict__ p2, const float* __restrict__ p1)
{
    int cx, cy, cz;
    if (blockIdx.x < 64) {
        int i = blockIdx.x * 256 + threadIdx.x;
        float x = p2[i * 3], y = p2[i * 3 + 1], z = p2[i * 3 + 2];
        int cell = cell_of(x, y, z, &cx, &cy, &cz);
        atomicAdd(&g_cnt[(i >> 12) * NCELL + cell], 1);
    } else {
        int i = (blockIdx.x - 64) * 256 + threadIdx.x;
        float x = p1[i * 3], y = p1[i * 3 + 1], z = p1[i * 3 + 2];
        int cell = cell_of(x, y, z, &cx, &cy, &cz);
        atomicAdd(&g_qcnt[(i >> 14) * NCELL + cell], 1);
    }
}

// scan both grids: blocks 0..3 points (writes cellStart+cellPtr), 4..7 queries (qptr)
__global__ __launch_bounds__(1024) void scan_all_kernel()
{
    __shared__ int ts[1024];
    bool isQ = blockIdx.x >= 4;
    int b = isQ ? blockIdx.x - 4 : blockIdx.x;
    const int* cnt = isQ ? g_qcnt : g_cnt;
    int* ptr = isQ ? g_qptr : g_cellPtr;
    int t = threadIdx.x;
    int v0 = cnt[b * NCELL + t * 4 + 0];
    int v1 = cnt[b * NCELL + t * 4 + 1];
    int v2 = cnt[b * NCELL + t * 4 + 2];
    int v3 = cnt[b * NCELL + t * 4 + 3];
    int loc = v0 + v1 + v2 + v3;
    ts[t] = loc;
    __syncthreads();
    for (int off = 1; off < 1024; off <<= 1) {
        int add = (t >= off) ? ts[t - off] : 0;
        __syncthreads();
        ts[t] += add;
        __syncthreads();
    }
    int p = ts[t] - loc;
    if (!isQ) {
        int base = b * (NCELL + 1);
        g_cellStart[base + t * 4 + 0] = p;
        g_cellStart[base + t * 4 + 1] = p + v0;
        g_cellStart[base + t * 4 + 2] = p + v0 + v1;
        g_cellStart[base + t * 4 + 3] = p + v0 + v1 + v2;
        if (t == 1023) g_cellStart[base + NCELL] = ts[1023];
    }
    ptr[b * NCELL + t * 4 + 0] = p;         p += v0;
    ptr[b * NCELL + t * 4 + 1] = p;         p += v1;
    ptr[b * NCELL + t * 4 + 2] = p;         p += v2;
    ptr[b * NCELL + t * 4 + 3] = p;
}

// scatter both (points blocks 0..63, queries 64..319)
__global__ void scatter_all_kernel(const float* __restrict__ p2, const float* __restrict__ p1)
{
    int cx, cy, cz;
    if (blockIdx.x < 64) {
        int i = blockIdx.x * 256 + threadIdx.x;
        int b = i >> 12;
        float x = p2[i * 3], y = p2[i * 3 + 1], z = p2[i * 3 + 2];
        float pp = __fadd_rn(__fadd_rn(__fmul_rn(x, x), __fmul_rn(y, y)), __fmul_rn(z, z));
        int cell = cell_of(x, y, z, &cx, &cy, &cz);
        int pos = atomicAdd(&g_cellPtr[b * NCELL + cell], 1);
        g_sortedPts[b * N2C + pos] = make_float4(x, y, z, pp);
        g_sortedIdx[b * N2C + pos] = i;
    } else {
        int i = (blockIdx.x - 64) * 256 + threadIdx.x;
        int b = i >> 14;
        float x = p1[i * 3], y = p1[i * 3 + 1], z = p1[i * 3 + 2];
        float qq = __fadd_rn(__fadd_rn(__fmul_rn(x, x), __fmul_rn(y, y)), __fmul_rn(z, z));
        int cell = cell_of(x, y, z, &cx, &cy, &cz);
        int pos = atomicAdd(&g_qptr[b * NCELL + cell], 1);
        g_sortedQ[b * N1C + pos] = make_float4(x, y, z, qq);
        g_sortedQid[b * N1C + pos] = i;
    }
}

// Make within-cell point order deterministic (ascending original index).
__global__ void grid_sortfix_kernel()
{
    int t = blockIdx.x * 256 + threadIdx.x;
    if (t >= CB * NCELL) return;
    int b = t >> 12, cell = t & 4095;
    int s = g_cellStart[b * (NCELL + 1) + cell];
    int e = g_cellStart[b * (NCELL + 1) + cell + 1];
    int base = b * N2C;
    for (int a = s + 1; a < e; a++) {
        int ia = g_sortedIdx[base + a];
        float4 pa = g_sortedPts[base + a];
        int k = a - 1;
        while (k >= s && g_sortedIdx[base + k] > ia) {
            g_sortedIdx[base + k + 1] = g_sortedIdx[base + k];
            g_sortedPts[base + k + 1] = g_sortedPts[base + k];
            k--;
        }
        g_sortedIdx[base + k + 1] = ia;
        g_sortedPts[base + k + 1] = pa;
    }
}

// ---------------- KNN (K=3) via grid ring expansion, cell-sorted queries -----
// Exactly emulates reference rounding (rn intrinsics, contraction-proof).
__global__ __launch_bounds__(256) void knn_kernel()
{
    extern __shared__ unsigned char smraw[];
    float4* sp = (float4*)smraw;                                  // 4096 float4
    int* cs  = (int*)(smraw + N2C * sizeof(float4));              // 4097 ints
    int* sid = (int*)(smraw + N2C * sizeof(float4) + (NCELL + 16) * sizeof(int)); // 4096 ints

    int pos = blockIdx.x * 256 + threadIdx.x;
    int batch = pos >> 14;
    for (int i = threadIdx.x; i < N2C; i += 256) {
        sp[i]  = g_sortedPts[batch * N2C + i];
        sid[i] = g_sortedIdx[batch * N2C + i];
    }
    for (int i = threadIdx.x; i < NCELL + 1; i += 256)
        cs[i] = g_cellStart[batch * (NCELL + 1) + i];
    __syncthreads();

    float4 qv = g_sortedQ[pos];
    int qid = g_sortedQid[pos];
    float qx = qv.x, qy = qv.y, qz = qv.z, qq = qv.w;

    int cx, cy, cz;
    (void)cell_of(qx, qy, qz, &cx, &cy, &cz);

    float b0 = 3.4e38f, b1 = 3.4e38f, b2 = 3.4e38f;
    int i0 = 0x7fffffff, i1 = 0x7fffffff, i2 = 0x7fffffff;

    auto proc = [&](int s, int e) {
        for (int j = s; j < e; j++) {
            float4 p = sp[j];
            int oi = sid[j];
            float dot = fmaf(qz, p.z, fmaf(qy, p.y, __fmul_rn(qx, p.x)));
            float d2 = __fsub_rn(__fadd_rn(qq, p.w), __fmul_rn(2.0f, dot));
            bool lt2 = (d2 < b2) || (d2 == b2 && oi < i2);
            if (lt2) {
                bool lt1 = (d2 < b1) || (d2 == b1 && oi < i1);
                if (lt1) {
                    b2 = b1; i2 = i1;
                    bool lt0 = (d2 < b0) || (d2 == b0 && oi < i0);
                    if (lt0) { b1 = b0; i1 = i0; b0 = d2; i0 = oi; }
                    else     { b1 = d2; i1 = oi; }
                } else { b2 = d2; i2 = oi; }
            }
        }
    };

    const float h = 0.0625f;
    int rmax = max(max(cx, 15 - cx), max(max(cy, 15 - cy), max(cz, 15 - cz)));
    for (int r = 0; r <= rmax; r++) {
        if (r > 0) {
            float bnd = (float)(r - 1) * h;   // all unvisited points are >= bnd away
            if (b2 <= bnd * bnd - 1e-6f) break;   // slack for fp32 rounding of d2
        }
        int zlo = max(cz - r, 0), zhi = min(cz + r, 15);
        for (int z = zlo; z <= zhi; z++) {
            bool ze = (z == cz - r) || (z == cz + r);
            int ylo = max(cy - r, 0), yhi = min(cy + r, 15);
            for (int y = ylo; y <= yhi; y++) {
                bool ye = (y == cy - r) || (y == cy + r);
                int rb = (z << 8) + (y << 4);
                if (ze || ye) {
                    int xlo = max(cx - r, 0), xhi = min(cx + r, 15);
                    proc(cs[rb + xlo], cs[rb + xhi + 1]);   // contiguous x-span
                } else {
                    if (cx - r >= 0) proc(cs[rb + cx - r], cs[rb + cx - r + 1]);
                    if (cx + r <= 15) proc(cs[rb + cx + r], cs[rb + cx + r + 1]);
                }
            }
        }
    }

    float d0 = fmaxf(b0, 0.f), d1 = fmaxf(b1, 0.f), d2c = fmaxf(b2, 0.f);
    float r0 = __fdiv_rn(1.0f, __fadd_rn(d0, 1e-8f));
    float r1 = __fdiv_rn(1.0f, __fadd_rn(d1, 1e-8f));
    float r2 = __fdiv_rn(1.0f, __fadd_rn(d2c, 1e-8f));
    float sum = __fadd_rn(__fadd_rn(r0, r1), r2);

    g_knnIdx[qid * 3 + 0] = i0;
    g_knnIdx[qid * 3 + 1] = i1;
    g_knnIdx[qid * 3 + 2] = i2;
    g_knnW[qid * 3 + 0] = __fdiv_rn(r0, sum);
    g_knnW[qid * 3 + 1] = __fdiv_rn(r1, sum);
    g_knnW[qid * 3 + 2] = __fdiv_rn(r2, sum);
}

// ---------------- final: BN+relu both branches, gather, weighted add ---------
// 8 rows per block; per-column BN params loaded once into registers.
#define FROWS 8
__global__ __launch_bounds__(256) void final_kernel(
    float* io,
    const float* __restrict__ ga1, const float* __restrict__ be1,
    const float* __restrict__ ga2, const float* __restrict__ be2)
{
    int row0 = blockIdx.x * FROWS, c = threadIdx.x;
    __shared__ int si[FROWS][3];
    __shared__ float sw[FROWS][3];
    if (c < FROWS * 3) {
        si[c / 3][c % 3] = g_knnIdx[row0 * 3 + c];
        sw[c / 3][c % 3] = g_knnW[row0 * 3 + c];
    }
    float G1 = ga1[c] * g_rstd1[c], B1 = be1[c], M1 = g_mean1[c];
    float G2 = ga2[c] * g_rstd2[c], B2 = be2[c], M2 = g_mean2[c];
    __syncthreads();

#pragma unroll
    for (int rr = 0; rr < FROWS; rr++) {
        int row = row0 + rr;
        float x = io[(size_t)row * COUTC + c];
        float v1 = fmaxf(G1 * (x - M1) + B1, 0.f);
        float acc = 0.f;
#pragma unroll
        for (int k = 0; k < 3; k++) {
            float y = g_f2pre[(size_t)si[rr][k] * COUTC + c];
            float v = fmaxf(G2 * (y - M2) + B2, 0.f);
            acc = fmaf(sw[rr][k], v, acc);
        }
        io[(size_t)row * COUTC + c] = v1 + acc;
    }
}

// ---------------- launch ----------------------------------------------------
extern "C" void kernel_launch(void* const* d_in, const int* in_sizes, int n_in,
                              void* d_out, int out_size)
{
    const float* p1  = (const float*)d_in[0];
    const float* f1  = (const float*)d_in[1];
    const float* p2  = (const float*)d_in[2];
    const float* f2  = (const float*)d_in[3];
    const float* W1  = (const float*)d_in[4];
    const float* b1  = (const float*)d_in[5];
    const float* ga1 = (const float*)d_in[6];
    const float* be1 = (const float*)d_in[7];
    const float* W2  = (const float*)d_in[8];
    const float* b2  = (const float*)d_in[9];
    const float* ga2 = (const float*)d_in[10];
    const float* be2 = (const float*)d_in[11];
    float* out = (float*)d_out;

    float *f2pre, *ps1, *pq1, *ps2, *pq2;
    __nv_bfloat16 *w1h, *w1l, *w2h, *w2l;
    cudaGetSymbolAddress((void**)&f2pre, g_f2pre);
    cudaGetSymbolAddress((void**)&ps1, g_psum1);
    cudaGetSymbolAddress((void**)&pq1, g_psq1);
    cudaGetSymbolAddress((void**)&ps2, g_psum2);
    cudaGetSymbolAddress((void**)&pq2, g_psq2);
    cudaGetSymbolAddress((void**)&w1h, g_W1h);
    cudaGetSymbolAddress((void**)&w1l, g_W1l);
    cudaGetSymbolAddress((void**)&w2h, g_W2h);
    cudaGetSymbolAddress((void**)&w2l, g_W2l);

    // 1: weight transpose + hi/lo split (both)
    wt_split_all_kernel<<<768, 256>>>(W1, W2);
    // 2-3: GEMMs (ncu capture lands here)
    gemm_mma_kernel<512><<<dim3(2, NP / 128), 256>>>(f2, w2h, w2l, b2, f2pre, ps2, pq2);
    gemm_mma_kernel<256><<<dim3(2, NQ / 128), 256>>>(f1, w1h, w1l, b1, out, ps1, pq1);
    // 4: BN stats final (both)
    colstats_final_all_kernel<<<512, 128>>>();
    // 5-9: spatial grids (points + queries)
    grid_zero_kernel<<<64, 256>>>();
    count_all_kernel<<<320, 256>>>(p2, p1);
    scan_all_kernel<<<8, 1024>>>();
    scatter_all_kernel<<<320, 256>>>(p2, p1);
    grid_sortfix_kernel<<<64, 256>>>();
    // 10: KNN  (smem: points 64KB + cellStart 16KB + ids 16KB)
    size_t sm = N2C * sizeof(float4) + (NCELL + 16) * sizeof(int) + N2C * sizeof(int);
    cudaFuncSetAttribute(knn_kernel, cudaFuncAttributeMaxDynamicSharedMemorySize, (int)sm);
    knn_kernel<<<256, 256, sm>>>();
    // 11: fused epilogue
    final_kernel<<<NQ / FROWS, 256>>>(out, ga1, be1, ga2, be2);
}